// round 5
// baseline (speedup 1.0000x reference)
#include <cuda_runtime.h>
#include <math.h>

#define NN    256
#define FEATD 1024
#define HIDR  256
#define HEADS 4
#define GCH   256
#define H1DIM 1024   // HEADS*GCH
#define OUTD  21
#define TOPK  3
#define E_TOT (NN*TOPK + NN)   // 1024 edges

// ---------------- scratch (device globals; no allocation allowed) ----------
__device__ __align__(16) float g_A[NN*HIDR];
__device__ __align__(16) float g_B[NN*HIDR];
__device__ __align__(16) float g_rel[NN*NN];
__device__ int   g_off[NN+1];
__device__ int   g_inc[E_TOT];
__device__ __align__(16) float g_h1[NN*H1DIM];
__device__ float g_ss1[NN*HEADS], g_ds1[NN*HEADS];
__device__ __align__(16) float g_x1[NN*H1DIM];
__device__ __align__(16) float g_h2[NN*OUTD];
__device__ float g_ss2[NN], g_ds2[NN];
__device__ __align__(16) float g_W2T[OUTD*H1DIM];   // W2 transposed [o][c]

// edge id -> source node (edges 0..767 are topk from row e/3; 768.. are loops)
__device__ __forceinline__ int edge_src(int e) {
    return (e < NN * TOPK) ? (e / TOPK) : (e - NN * TOPK);
}

// read a scalar that may have been serialized as int32 or float32
__device__ __forceinline__ float read_dim(const void* p) {
    int iv = *(const int*)p;
    if (iv > 0 && iv < 100000) return (float)iv;
    return *(const float*)p;
}

// ---------------- K1: A = F @ W_fc1[0:1024], B = F @ W_fc1[1024:2048] ------
__global__ void k_ab(const float* __restrict__ feat, const float* __restrict__ Wfc1) {
    __shared__ float  sA[16][33];
    __shared__ float4 sW[16][16];
    int t = threadIdx.x;
    int tx = t & 15, ty = t >> 4;
    int row0 = blockIdx.y * 32;
    int colg = blockIdx.x * 64;
    const float* W;
    float* dst;
    int colL;
    if (colg < 256) { W = Wfc1;                       dst = g_A; colL = colg; }
    else            { W = Wfc1 + (size_t)1024 * HIDR; dst = g_B; colL = colg - 256; }
    float acc[2][4] = {};
    for (int k0 = 0; k0 < FEATD; k0 += 16) {
        if (t < 128) {
            int r = t >> 2, kq = t & 3;
            float4 v = *(const float4*)&feat[(size_t)(row0 + r) * FEATD + k0 + kq * 4];
            sA[kq*4+0][r] = v.x; sA[kq*4+1][r] = v.y; sA[kq*4+2][r] = v.z; sA[kq*4+3][r] = v.w;
        }
        {
            int kr = t >> 4, cq = t & 15;
            sW[kr][cq] = *(const float4*)&W[(size_t)(k0 + kr) * HIDR + colL + cq * 4];
        }
        __syncthreads();
#pragma unroll
        for (int kk = 0; kk < 16; kk++) {
            float a0 = sA[kk][ty], a1 = sA[kk][ty + 16];
            float4 w = sW[kk][tx];
            acc[0][0] += a0 * w.x; acc[0][1] += a0 * w.y; acc[0][2] += a0 * w.z; acc[0][3] += a0 * w.w;
            acc[1][0] += a1 * w.x; acc[1][1] += a1 * w.y; acc[1][2] += a1 * w.z; acc[1][3] += a1 * w.w;
        }
        __syncthreads();
    }
#pragma unroll
    for (int u = 0; u < 2; u++) {
        int r = row0 + ty + u * 16;
        *(float4*)&dst[(size_t)r * HIDR + colL + tx * 4] =
            make_float4(acc[u][0], acc[u][1], acc[u][2], acc[u][3]);
    }
}

// ---------------- K2: rel[i,j] = relu(A[i]+B[j]+bias+geom@Wg) . W_fc2 + b2 -
__global__ void k_rel(const float* __restrict__ boxes,
                      const float* __restrict__ Wfc1,
                      const float* __restrict__ bfc1,
                      const float* __restrict__ Wfc2,
                      const float* __restrict__ bfc2) {
    __shared__ __align__(16) float sAb[8][HIDR];
    __shared__ __align__(16) float sBt[HIDR][68];
    __shared__ __align__(16) float4 sGeo[HIDR];
    __shared__ float sW2[HIDR];
    int t = threadIdx.x;                 // 128
    int il = t >> 4, jg = t & 15, jl = jg * 4;
    int i0 = blockIdx.y * 8, j0 = blockIdx.x * 64;
    const float* Wg = Wfc1 + (size_t)2 * FEATD * HIDR;
    for (int idx = t; idx < 8 * HIDR; idx += 128) {
        int i = idx >> 8, c = idx & 255;
        sAb[i][c] = g_A[(size_t)(i0 + i) * HIDR + c] + bfc1[c];
    }
    for (int idx = t; idx < 64 * HIDR; idx += 128) {
        int j = idx >> 8, c = idx & 255;
        sBt[c][j] = g_B[(size_t)(j0 + j) * HIDR + c];
    }
    for (int c = t; c < HIDR; c += 128) {
        sGeo[c] = make_float4(Wg[c], Wg[HIDR + c], Wg[2 * HIDR + c], Wg[3 * HIDR + c]);
        sW2[c] = Wfc2[c];
    }
    __syncthreads();
    int ig = i0 + il;
    float bi0 = boxes[ig*4+0], bi1 = boxes[ig*4+1], bi2 = boxes[ig*4+2], bi3 = boxes[ig*4+3];
    float4 G[4];
#pragma unroll
    for (int q = 0; q < 4; q++) {
        int jgl = j0 + jl + q;
        G[q] = make_float4(fabsf(bi0 - boxes[jgl*4+0]), fabsf(bi1 - boxes[jgl*4+1]),
                           fabsf(bi2 - boxes[jgl*4+2]), fabsf(bi3 - boxes[jgl*4+3]));
    }
    float acc[4] = {};
#pragma unroll 4
    for (int c = 0; c < HIDR; c++) {
        float  a  = sAb[il][c];
        float4 wg = sGeo[c];
        float  w2 = sW2[c];
        float4 b4 = *(const float4*)&sBt[c][jl];
        float v0 = a + b4.x + G[0].x*wg.x + G[0].y*wg.y + G[0].z*wg.z + G[0].w*wg.w;
        float v1 = a + b4.y + G[1].x*wg.x + G[1].y*wg.y + G[1].z*wg.z + G[1].w*wg.w;
        float v2 = a + b4.z + G[2].x*wg.x + G[2].y*wg.y + G[2].z*wg.z + G[2].w*wg.w;
        float v3 = a + b4.w + G[3].x*wg.x + G[3].y*wg.y + G[3].z*wg.z + G[3].w*wg.w;
        acc[0] += fmaxf(v0, 0.f) * w2;
        acc[1] += fmaxf(v1, 0.f) * w2;
        acc[2] += fmaxf(v2, 0.f) * w2;
        acc[3] += fmaxf(v3, 0.f) * w2;
    }
    float bb = bfc2[0];
#pragma unroll
    for (int q = 0; q < 4; q++)
        g_rel[(size_t)ig * NN + j0 + jl + q] = acc[q] + bb;
}

// ---------------- K3: fused top-k + CSR build (one block, 1024 threads) ----
// Phase 1: warp-per-row top-4 (rows strided over 32 warps), results in smem.
// Phase 2: sort-free deterministic CSR (match_any rank within warp-chunk +
// chunk-prefix + node-prefix) == exact ascending-edge-id bucket order.
// Side job: W2 transpose into g_W2T.
__global__ void k_topk_edges(const float* __restrict__ W2) {
    int t = threadIdx.x;                 // 0..1023
    int lane = t & 31, w = t >> 5;       // 32 warps
    __shared__ int sTop[NN * TOPK];
    __shared__ int M[32][NN];            // chunk x node counts -> excl. prefixes
    __shared__ int off[NN];
    for (int idx = t; idx < 32 * NN; idx += 1024) ((int*)M)[idx] = 0;
    // ---- top-k ----
    for (int i = w; i < NN; i += 32) {
        float v[8];
#pragma unroll
        for (int q = 0; q < 8; q++) v[q] = g_rel[i * NN + q * 32 + lane];
#pragma unroll
        for (int sel = 0; sel < TOPK + 1; sel++) {
            float bv = -INFINITY; int bi = 0;
#pragma unroll
            for (int q = 0; q < 8; q++) {
                int idx = q * 32 + lane;
                if (v[q] > bv) { bv = v[q]; bi = idx; }   // '>' keeps smallest idx in-lane
            }
#pragma unroll
            for (int o = 16; o; o >>= 1) {
                float ov = __shfl_down_sync(0xffffffffu, bv, o);
                int   oi = __shfl_down_sync(0xffffffffu, bi, o);
                if (ov > bv || (ov == bv && oi < bi)) { bv = ov; bi = oi; }  // tie -> smaller idx
            }
            bi = __shfl_sync(0xffffffffu, bi, 0);
            if (sel > 0 && lane == 0) sTop[i * TOPK + sel - 1] = bi;
            if ((bi & 31) == lane) v[bi >> 5] = -INFINITY;
        }
    }
    // ---- W2 transpose side job ----
    for (int idx = t; idx < OUTD * H1DIM; idx += 1024) {
        int o = idx / H1DIM, c = idx - o * H1DIM;
        g_W2T[idx] = W2[c * OUTD + o];
    }
    __syncthreads();
    // ---- CSR build ----
    int e = t;
    int tg = (e < NN * TOPK) ? sTop[e] : (e - NN * TOPK);
    unsigned same = __match_any_sync(0xffffffffu, tg);
    int rank = __popc(same & ((1u << lane) - 1u));
    if (rank == 0) M[w][tg] = __popc(same);   // leader lane writes chunk count
    __syncthreads();
    if (t < NN) {
        int run = 0;
#pragma unroll
        for (int cc = 0; cc < 32; cc++) { int v = M[cc][t]; M[cc][t] = run; run += v; }
        off[t] = run;
    }
    __syncthreads();
    for (int s = 1; s < NN; s <<= 1) {
        int v = 0;
        if (t < NN && t >= s) v = off[t - s];
        __syncthreads();
        if (t < NN) off[t] += v;
        __syncthreads();
    }
    if (t < NN) {
        g_off[t + 1] = off[t];
        if (t == 0) g_off[0] = 0;
    }
    __syncthreads();
    int base = (tg == 0) ? 0 : off[tg - 1];
    g_inc[base + M[w][tg] + rank] = e;
}

// ---------------- K5: h1 = [features | geomn] @ W1 (tiled GEMM) ------------
__global__ void k_gemm1(const float* __restrict__ feat,
                        const float* __restrict__ boxes,
                        const float* __restrict__ W1,
                        const void* img_h, const void* img_w) {
    __shared__ float  sA[16][33];
    __shared__ float4 sW[16][16];
    int t = threadIdx.x;
    int tx = t & 15, ty = t >> 4;
    int row0 = blockIdx.y * 32;
    int col0 = blockIdx.x * 64;
    float acc[2][4] = {};
    for (int k0 = 0; k0 < FEATD; k0 += 16) {
        if (t < 128) {
            int r = t >> 2, kq = t & 3;
            float4 v = *(const float4*)&feat[(size_t)(row0 + r) * FEATD + k0 + kq * 4];
            sA[kq*4+0][r] = v.x; sA[kq*4+1][r] = v.y; sA[kq*4+2][r] = v.z; sA[kq*4+3][r] = v.w;
        }
        {
            int kr = t >> 4, cq = t & 15;
            sW[kr][cq] = *(const float4*)&W1[(size_t)(k0 + kr) * H1DIM + col0 + cq * 4];
        }
        __syncthreads();
#pragma unroll
        for (int kk = 0; kk < 16; kk++) {
            float a0 = sA[kk][ty], a1 = sA[kk][ty + 16];
            float4 w = sW[kk][tx];
            acc[0][0] += a0 * w.x; acc[0][1] += a0 * w.y; acc[0][2] += a0 * w.z; acc[0][3] += a0 * w.w;
            acc[1][0] += a1 * w.x; acc[1][1] += a1 * w.y; acc[1][2] += a1 * w.z; acc[1][3] += a1 * w.w;
        }
        __syncthreads();
    }
    float fw = read_dim(img_w), fh = read_dim(img_h);
#pragma unroll
    for (int u = 0; u < 2; u++) {
        int n = row0 + ty + u * 16;
        float b0 = boxes[n*4+0] / fw, b1 = boxes[n*4+1] / fh;
        float b2 = boxes[n*4+2] / fw, b3 = boxes[n*4+3] / fh;
        float G[4] = { b0, b1, b2 - b0, b3 - b1 };
#pragma unroll
        for (int kk = 0; kk < 4; kk++) {
            const float* wr = &W1[(size_t)(FEATD + kk) * H1DIM + col0 + tx * 4];
            acc[u][0] += G[kk] * wr[0];
            acc[u][1] += G[kk] * wr[1];
            acc[u][2] += G[kk] * wr[2];
            acc[u][3] += G[kk] * wr[3];
        }
        *(float4*)&g_h1[(size_t)n * H1DIM + col0 + tx * 4] =
            make_float4(acc[u][0], acc[u][1], acc[u][2], acc[u][3]);
    }
}

// ---------------- K6: per-node per-head attention scores (layer 1) ---------
__global__ void k_score1(const float* __restrict__ a_src,
                         const float* __restrict__ a_dst) {
    int n = blockIdx.x;
    int hd = threadIdx.x >> 5, lane = threadIdx.x & 31;
    float s = 0.f, d = 0.f;
    for (int c = lane; c < GCH; c += 32) {
        float hv = g_h1[n * H1DIM + hd * GCH + c];
        s += hv * a_src[hd * GCH + c];
        d += hv * a_dst[hd * GCH + c];
    }
#pragma unroll
    for (int o = 16; o; o >>= 1) {
        s += __shfl_down_sync(0xffffffffu, s, o);
        d += __shfl_down_sync(0xffffffffu, d, o);
    }
    if (!lane) { g_ss1[n * HEADS + hd] = s; g_ds1[n * HEADS + hd] = d; }
}

// ---------------- K7: GAT1 softmax aggregation + bias + relu ---------------
__global__ void k_gat1(const float* __restrict__ b1) {
    int tnode = blockIdx.x, tid = threadIdx.x;
    int off = g_off[tnode], cnt = g_off[tnode + 1] - off;
    __shared__ float al[E_TOT * HEADS];
    for (int idx = tid; idx < cnt * HEADS; idx += blockDim.x) {
        int k = idx >> 2, hd = idx & 3;
        int sn = edge_src(g_inc[off + k]);
        float x = g_ss1[sn * HEADS + hd] + g_ds1[tnode * HEADS + hd];
        al[idx] = (x >= 0.f) ? x : 0.2f * x;   // leaky_relu 0.2
    }
    __syncthreads();
    if (tid < HEADS) {
        float m = -INFINITY;
        for (int k = 0; k < cnt; k++) m = fmaxf(m, al[k * HEADS + tid]);
        float s = 0.f;
        for (int k = 0; k < cnt; k++) { float p = expf(al[k * HEADS + tid] - m); al[k * HEADS + tid] = p; s += p; }
        float inv = 1.f / s;
        for (int k = 0; k < cnt; k++) al[k * HEADS + tid] *= inv;
    }
    __syncthreads();
    for (int o = tid; o < H1DIM; o += blockDim.x) {
        int hd = o >> 8;
        float acc = 0.f;
        for (int k = 0; k < cnt; k++) {
            int sn = edge_src(g_inc[off + k]);
            acc += al[k * HEADS + hd] * g_h1[sn * H1DIM + o];
        }
        g_x1[tnode * H1DIM + o] = fmaxf(acc + b1[o], 0.f);
    }
}

// ---------------- K8: h2 = x1 @ W2T + layer-2 attention scores -------------
__global__ void k_gemm2(const float* __restrict__ a_src,
                        const float* __restrict__ a_dst) {
    int n = blockIdx.x, t = threadIdx.x;     // 256 threads
    int w = t >> 5, lane = t & 31;
    __shared__ __align__(16) float sX[H1DIM];
    __shared__ float lg[OUTD];
    for (int c = t; c < H1DIM; c += 256) sX[c] = g_x1[n * H1DIM + c];
    __syncthreads();
    for (int o = w; o < OUTD; o += 8) {
        float acc = 0.f;
        const float* wr = &g_W2T[o * H1DIM];
        for (int c = lane; c < H1DIM; c += 32)
            acc += sX[c] * wr[c];
#pragma unroll
        for (int s = 16; s; s >>= 1) acc += __shfl_down_sync(0xffffffffu, acc, s);
        if (!lane) { g_h2[n * OUTD + o] = acc; lg[o] = acc; }
    }
    __syncthreads();
    if (t == 0) {
        float s = 0.f, d = 0.f;
        for (int oo = 0; oo < OUTD; oo++) {
            s += lg[oo] * a_src[oo];
            d += lg[oo] * a_dst[oo];
        }
        g_ss2[n] = s; g_ds2[n] = d;
    }
}

// ---------------- K10: GAT2 aggregate -> logits + argmax labels ------------
__global__ void k_gat2(const float* __restrict__ b2, float* __restrict__ out,
                       int out_size) {
    int tnode = blockIdx.x, tid = threadIdx.x;   // block of 32
    int off = g_off[tnode], cnt = g_off[tnode + 1] - off;
    __shared__ float al[E_TOT];
    __shared__ float lg[OUTD];
    for (int k = tid; k < cnt; k += 32) {
        int sn = edge_src(g_inc[off + k]);
        float x = g_ss2[sn] + g_ds2[tnode];
        al[k] = (x >= 0.f) ? x : 0.2f * x;
    }
    __syncthreads();
    if (tid == 0) {
        float m = -INFINITY;
        for (int k = 0; k < cnt; k++) m = fmaxf(m, al[k]);
        float s = 0.f;
        for (int k = 0; k < cnt; k++) { float p = expf(al[k] - m); al[k] = p; s += p; }
        float inv = 1.f / s;
        for (int k = 0; k < cnt; k++) al[k] *= inv;
    }
    __syncthreads();
    for (int o = tid; o < OUTD; o += 32) {
        float acc = 0.f;
        for (int k = 0; k < cnt; k++) {
            int sn = edge_src(g_inc[off + k]);
            acc += al[k] * g_h2[sn * OUTD + o];
        }
        float v = acc + b2[o];
        lg[o] = v;
        out[tnode * OUTD + o] = v;
    }
    __syncthreads();
    if (tid == 0 && out_size >= NN * OUTD + NN) {
        int best = 0;
        float bv = lg[0];
        for (int o = 1; o < OUTD; o++)
            if (lg[o] > bv) { bv = lg[o]; best = o; }
        out[NN * OUTD + tnode] = (float)best;
    }
}

// ---------------------------------------------------------------------------
extern "C" void kernel_launch(void* const* d_in, const int* in_sizes, int n_in,
                              void* d_out, int out_size) {
    const float* features = (const float*)d_in[0];
    const float* boxes    = (const float*)d_in[1];
    const float* W_fc1    = (const float*)d_in[2];
    const float* b_fc1    = (const float*)d_in[3];
    const float* W_fc2    = (const float*)d_in[4];
    const float* b_fc2    = (const float*)d_in[5];
    const float* W1       = (const float*)d_in[6];
    const float* a_src1   = (const float*)d_in[7];
    const float* a_dst1   = (const float*)d_in[8];
    const float* b1       = (const float*)d_in[9];
    const float* W2       = (const float*)d_in[10];
    const float* a_src2   = (const float*)d_in[11];
    const float* a_dst2   = (const float*)d_in[12];
    const float* b2       = (const float*)d_in[13];
    const void*  img_h    = d_in[14];
    const void*  img_w    = d_in[15];
    float* out = (float*)d_out;

    // side stream + events (created once; same GPU work every call)
    static cudaStream_t s1 = nullptr;
    static cudaEvent_t  e0 = nullptr, e1 = nullptr;
    if (!s1) {
        cudaStreamCreateWithFlags(&s1, cudaStreamNonBlocking);
        cudaEventCreateWithFlags(&e0, cudaEventDisableTiming);
        cudaEventCreateWithFlags(&e1, cudaEventDisableTiming);
    }

    // fork: main chain = rel-graph construction; side chain = GAT input GEMM
    cudaEventRecord(e0, 0);
    cudaStreamWaitEvent(s1, e0, 0);

    // main chain (capture-origin stream)
    k_ab<<<dim3(8, 8), 256>>>(features, W_fc1);
    k_rel<<<dim3(4, 32), 128>>>(boxes, W_fc1, b_fc1, W_fc2, b_fc2);
    k_topk_edges<<<1, 1024>>>(W2);

    // side chain
    k_gemm1<<<dim3(16, 8), 256, 0, s1>>>(features, boxes, W1, img_h, img_w);
    k_score1<<<NN, 128, 0, s1>>>(a_src1, a_dst1);

    // join
    cudaEventRecord(e1, s1);
    cudaStreamWaitEvent(0, e1, 0);

    // tail
    k_gat1<<<NN, 256>>>(b1);
    k_gemm2<<<NN, 256>>>(a_src2, a_dst2);
    k_gat2<<<NN, 32>>>(b2, out, out_size);
}

// round 6
// speedup vs baseline: 1.2316x; 1.2316x over previous
#include <cuda_runtime.h>
#include <math.h>

#define NN    256
#define FEATD 1024
#define HIDR  256
#define HEADS 4
#define GCH   256
#define H1DIM 1024   // HEADS*GCH
#define OUTD  21
#define TOPK  3
#define E_TOT (NN*TOPK + NN)   // 1024 edges

// ---------------- scratch (device globals; no allocation allowed) ----------
__device__ __align__(16) float g_A[NN*HIDR];
__device__ __align__(16) float g_B[NN*HIDR];
__device__ __align__(16) float g_rel[NN*NN];
__device__ int   g_off[NN+1];
__device__ int   g_inc[E_TOT];
__device__ __align__(16) float g_h1[NN*H1DIM];
__device__ float g_ss1[NN*HEADS], g_ds1[NN*HEADS];
__device__ __align__(16) float g_x1[NN*H1DIM];
__device__ __align__(16) float g_h2[NN*OUTD];
__device__ float g_ss2[NN], g_ds2[NN];
__device__ __align__(16) float g_W2T[OUTD*H1DIM];   // W2 transposed [o][c]

// edge id -> source node (edges 0..767 are topk from row e/3; 768.. are loops)
__device__ __forceinline__ int edge_src(int e) {
    return (e < NN * TOPK) ? (e / TOPK) : (e - NN * TOPK);
}

// read a scalar that may have been serialized as int32 or float32
__device__ __forceinline__ float read_dim(const void* p) {
    int iv = *(const int*)p;
    if (iv > 0 && iv < 100000) return (float)iv;
    return *(const float*)p;
}

// ============ shared SGEMM core: BM=32, BN=64, BK=16, 128 thr, 4x4 =========
// Thread layout: tx = t&15 (col quad), ty = t>>4 (row quad). acc[4][4].
// A: [M x lda] row-major, tile rows row0..row0+31, k-major.
// W: [K x ldw] row-major, tile cols col0..col0+63.
// Register-prefetch double buffering over k-tiles.
struct SgemmAcc { float a[4][4]; };

__device__ __forceinline__ void sgemm_core_32x64(
    const float* __restrict__ Abase, int lda,
    const float* __restrict__ Wbase, int ldw,
    int row0, int col0, int K, SgemmAcc& acc,
    float (*sAT)[36], float (*sW)[64])
{
    int t = threadIdx.x;
    int arow = t >> 2, akq = t & 3;        // A loader: 32 rows x 4 k-quads
    int wkr = t >> 3, wcq = t & 7;         // W loader: 16 k-rows x 8 col-pairs
    int tx4 = (t & 15) * 4, ty4 = (t >> 4) * 4;
    const float* Aptr = Abase + (size_t)(row0 + arow) * lda + akq * 4;
    const float* Wptr = Wbase + (size_t)wkr * ldw + col0 + wcq * 8;
    int KT = K >> 4;
    float4 pa = *(const float4*)Aptr;
    float4 pw0 = *(const float4*)Wptr;
    float4 pw1 = *(const float4*)(Wptr + 4);
    for (int kt = 0; kt < KT; kt++) {
        // store current tile
        sAT[akq*4+0][arow] = pa.x;
        sAT[akq*4+1][arow] = pa.y;
        sAT[akq*4+2][arow] = pa.z;
        sAT[akq*4+3][arow] = pa.w;
        *(float4*)&sW[wkr][wcq*8]     = pw0;
        *(float4*)&sW[wkr][wcq*8 + 4] = pw1;
        __syncthreads();
        // prefetch next tile (overlaps with compute below)
        if (kt + 1 < KT) {
            const float* An = Aptr + (kt + 1) * 16;
            const float* Wn = Wptr + (size_t)(kt + 1) * 16 * ldw;
            pa  = *(const float4*)An;
            pw0 = *(const float4*)Wn;
            pw1 = *(const float4*)(Wn + 4);
        }
#pragma unroll
        for (int kk = 0; kk < 16; kk++) {
            float4 a = *(const float4*)&sAT[kk][ty4];
            float4 w = *(const float4*)&sW[kk][tx4];
            acc.a[0][0] += a.x * w.x; acc.a[0][1] += a.x * w.y; acc.a[0][2] += a.x * w.z; acc.a[0][3] += a.x * w.w;
            acc.a[1][0] += a.y * w.x; acc.a[1][1] += a.y * w.y; acc.a[1][2] += a.y * w.z; acc.a[1][3] += a.y * w.w;
            acc.a[2][0] += a.z * w.x; acc.a[2][1] += a.z * w.y; acc.a[2][2] += a.z * w.z; acc.a[2][3] += a.z * w.w;
            acc.a[3][0] += a.w * w.x; acc.a[3][1] += a.w * w.y; acc.a[3][2] += a.w * w.z; acc.a[3][3] += a.w * w.w;
        }
        __syncthreads();
    }
}

// ---------------- K1: [g_A | g_B] = F @ W_fc1[0:2048] ----------------------
// Grid: x = 8 col-blocks (512 cols), y = 8 row-blocks. 128 threads.
__global__ void k_ab(const float* __restrict__ feat, const float* __restrict__ Wfc1) {
    __shared__ float sAT[16][36];
    __shared__ float sW[16][64];
    int col0 = blockIdx.x * 64;
    int row0 = blockIdx.y * 32;
    const float* W;
    float* dst;
    int colL;
    if (col0 < 256) { W = Wfc1;                       dst = g_A; colL = col0; }
    else            { W = Wfc1 + (size_t)1024 * HIDR; dst = g_B; colL = col0 - 256; }
    SgemmAcc acc = {};
    sgemm_core_32x64(feat, FEATD, W, HIDR, row0, colL, FEATD, acc, sAT, sW);
    int tx4 = (threadIdx.x & 15) * 4, ty4 = (threadIdx.x >> 4) * 4;
#pragma unroll
    for (int u = 0; u < 4; u++) {
        int r = row0 + ty4 + u;
        *(float4*)&dst[(size_t)r * HIDR + colL + tx4] =
            make_float4(acc.a[u][0], acc.a[u][1], acc.a[u][2], acc.a[u][3]);
    }
}

// ---------------- K5: h1 = [features | geomn] @ W1 -------------------------
// Grid: x = 16 col-blocks (1024 cols), y = 8 row-blocks. 128 threads.
__global__ void k_gemm1(const float* __restrict__ feat,
                        const float* __restrict__ boxes,
                        const float* __restrict__ W1,
                        const void* img_h, const void* img_w) {
    __shared__ float sAT[16][36];
    __shared__ float sW[16][64];
    int col0 = blockIdx.x * 64;
    int row0 = blockIdx.y * 32;
    SgemmAcc acc = {};
    sgemm_core_32x64(feat, FEATD, W1, H1DIM, row0, col0, FEATD, acc, sAT, sW);
    int tx4 = (threadIdx.x & 15) * 4, ty4 = (threadIdx.x >> 4) * 4;
    float fw = read_dim(img_w), fh = read_dim(img_h);
#pragma unroll
    for (int u = 0; u < 4; u++) {
        int n = row0 + ty4 + u;
        float b0 = boxes[n*4+0] / fw, b1 = boxes[n*4+1] / fh;
        float b2 = boxes[n*4+2] / fw, b3 = boxes[n*4+3] / fh;
        float G[4] = { b0, b1, b2 - b0, b3 - b1 };
#pragma unroll
        for (int kk = 0; kk < 4; kk++) {
            float4 w = *(const float4*)&W1[(size_t)(FEATD + kk) * H1DIM + col0 + tx4];
            acc.a[u][0] += G[kk] * w.x;
            acc.a[u][1] += G[kk] * w.y;
            acc.a[u][2] += G[kk] * w.z;
            acc.a[u][3] += G[kk] * w.w;
        }
        *(float4*)&g_h1[(size_t)n * H1DIM + col0 + tx4] =
            make_float4(acc.a[u][0], acc.a[u][1], acc.a[u][2], acc.a[u][3]);
    }
}

// ---------------- K2: rel[i,j] = relu(A[i]+B[j]+bias+geom@Wg) . W_fc2 + b2 -
__global__ void k_rel(const float* __restrict__ boxes,
                      const float* __restrict__ Wfc1,
                      const float* __restrict__ bfc1,
                      const float* __restrict__ Wfc2,
                      const float* __restrict__ bfc2) {
    __shared__ __align__(16) float sAb[8][HIDR];
    __shared__ __align__(16) float sBt[HIDR][68];
    __shared__ __align__(16) float4 sGeo[HIDR];
    __shared__ float sW2[HIDR];
    int t = threadIdx.x;                 // 128
    int il = t >> 4, jg = t & 15, jl = jg * 4;
    int i0 = blockIdx.y * 8, j0 = blockIdx.x * 64;
    const float* Wg = Wfc1 + (size_t)2 * FEATD * HIDR;
    for (int idx = t; idx < 8 * HIDR; idx += 128) {
        int i = idx >> 8, c = idx & 255;
        sAb[i][c] = g_A[(size_t)(i0 + i) * HIDR + c] + bfc1[c];
    }
    for (int idx = t; idx < 64 * HIDR; idx += 128) {
        int j = idx >> 8, c = idx & 255;
        sBt[c][j] = g_B[(size_t)(j0 + j) * HIDR + c];
    }
    for (int c = t; c < HIDR; c += 128) {
        sGeo[c] = make_float4(Wg[c], Wg[HIDR + c], Wg[2 * HIDR + c], Wg[3 * HIDR + c]);
        sW2[c] = Wfc2[c];
    }
    __syncthreads();
    int ig = i0 + il;
    float bi0 = boxes[ig*4+0], bi1 = boxes[ig*4+1], bi2 = boxes[ig*4+2], bi3 = boxes[ig*4+3];
    float4 G[4];
#pragma unroll
    for (int q = 0; q < 4; q++) {
        int jgl = j0 + jl + q;
        G[q] = make_float4(fabsf(bi0 - boxes[jgl*4+0]), fabsf(bi1 - boxes[jgl*4+1]),
                           fabsf(bi2 - boxes[jgl*4+2]), fabsf(bi3 - boxes[jgl*4+3]));
    }
    float acc[4] = {};
#pragma unroll 4
    for (int c = 0; c < HIDR; c++) {
        float  a  = sAb[il][c];
        float4 wg = sGeo[c];
        float  w2 = sW2[c];
        float4 b4 = *(const float4*)&sBt[c][jl];
        float v0 = a + b4.x + G[0].x*wg.x + G[0].y*wg.y + G[0].z*wg.z + G[0].w*wg.w;
        float v1 = a + b4.y + G[1].x*wg.x + G[1].y*wg.y + G[1].z*wg.z + G[1].w*wg.w;
        float v2 = a + b4.z + G[2].x*wg.x + G[2].y*wg.y + G[2].z*wg.z + G[2].w*wg.w;
        float v3 = a + b4.w + G[3].x*wg.x + G[3].y*wg.y + G[3].z*wg.z + G[3].w*wg.w;
        acc[0] += fmaxf(v0, 0.f) * w2;
        acc[1] += fmaxf(v1, 0.f) * w2;
        acc[2] += fmaxf(v2, 0.f) * w2;
        acc[3] += fmaxf(v3, 0.f) * w2;
    }
    float bb = bfc2[0];
#pragma unroll
    for (int q = 0; q < 4; q++)
        g_rel[(size_t)ig * NN + j0 + jl + q] = acc[q] + bb;
}

// ---------------- K3: fused top-k + CSR build (one block, 1024 threads) ----
__global__ void k_topk_edges(const float* __restrict__ W2) {
    int t = threadIdx.x;                 // 0..1023
    int lane = t & 31, w = t >> 5;       // 32 warps
    __shared__ int sTop[NN * TOPK];
    __shared__ int M[32][NN];            // chunk x node counts -> excl. prefixes
    __shared__ int off[NN];
    for (int idx = t; idx < 32 * NN; idx += 1024) ((int*)M)[idx] = 0;
    // ---- top-k ----
    for (int i = w; i < NN; i += 32) {
        float v[8];
#pragma unroll
        for (int q = 0; q < 8; q++) v[q] = g_rel[i * NN + q * 32 + lane];
#pragma unroll
        for (int sel = 0; sel < TOPK + 1; sel++) {
            float bv = -INFINITY; int bi = 0;
#pragma unroll
            for (int q = 0; q < 8; q++) {
                int idx = q * 32 + lane;
                if (v[q] > bv) { bv = v[q]; bi = idx; }
            }
#pragma unroll
            for (int o = 16; o; o >>= 1) {
                float ov = __shfl_down_sync(0xffffffffu, bv, o);
                int   oi = __shfl_down_sync(0xffffffffu, bi, o);
                if (ov > bv || (ov == bv && oi < bi)) { bv = ov; bi = oi; }
            }
            bi = __shfl_sync(0xffffffffu, bi, 0);
            if (sel > 0 && lane == 0) sTop[i * TOPK + sel - 1] = bi;
            if ((bi & 31) == lane) v[bi >> 5] = -INFINITY;
        }
    }
    // ---- W2 transpose side job ----
    for (int idx = t; idx < OUTD * H1DIM; idx += 1024) {
        int o = idx / H1DIM, c = idx - o * H1DIM;
        g_W2T[idx] = W2[c * OUTD + o];
    }
    __syncthreads();
    // ---- CSR build (sort-free, deterministic) ----
    int e = t;
    int tg = (e < NN * TOPK) ? sTop[e] : (e - NN * TOPK);
    unsigned same = __match_any_sync(0xffffffffu, tg);
    int rank = __popc(same & ((1u << lane) - 1u));
    if (rank == 0) M[w][tg] = __popc(same);
    __syncthreads();
    if (t < NN) {
        int run = 0;
#pragma unroll
        for (int cc = 0; cc < 32; cc++) { int v = M[cc][t]; M[cc][t] = run; run += v; }
        off[t] = run;
    }
    __syncthreads();
    for (int s = 1; s < NN; s <<= 1) {
        int v = 0;
        if (t < NN && t >= s) v = off[t - s];
        __syncthreads();
        if (t < NN) off[t] += v;
        __syncthreads();
    }
    if (t < NN) {
        g_off[t + 1] = off[t];
        if (t == 0) g_off[0] = 0;
    }
    __syncthreads();
    int base = (tg == 0) ? 0 : off[tg - 1];
    g_inc[base + M[w][tg] + rank] = e;
}

// ---------------- K6: per-node per-head attention scores (layer 1) ---------
__global__ void k_score1(const float* __restrict__ a_src,
                         const float* __restrict__ a_dst) {
    int n = blockIdx.x;
    int hd = threadIdx.x >> 5, lane = threadIdx.x & 31;
    float s = 0.f, d = 0.f;
    for (int c = lane; c < GCH; c += 32) {
        float hv = g_h1[n * H1DIM + hd * GCH + c];
        s += hv * a_src[hd * GCH + c];
        d += hv * a_dst[hd * GCH + c];
    }
#pragma unroll
    for (int o = 16; o; o >>= 1) {
        s += __shfl_down_sync(0xffffffffu, s, o);
        d += __shfl_down_sync(0xffffffffu, d, o);
    }
    if (!lane) { g_ss1[n * HEADS + hd] = s; g_ds1[n * HEADS + hd] = d; }
}

// ---------------- K7: GAT1 softmax aggregation + bias + relu ---------------
__global__ void k_gat1(const float* __restrict__ b1) {
    int tnode = blockIdx.x, tid = threadIdx.x;
    int off = g_off[tnode], cnt = g_off[tnode + 1] - off;
    __shared__ float al[E_TOT * HEADS];
    for (int idx = tid; idx < cnt * HEADS; idx += blockDim.x) {
        int k = idx >> 2, hd = idx & 3;
        int sn = edge_src(g_inc[off + k]);
        float x = g_ss1[sn * HEADS + hd] + g_ds1[tnode * HEADS + hd];
        al[idx] = (x >= 0.f) ? x : 0.2f * x;   // leaky_relu 0.2
    }
    __syncthreads();
    if (tid < HEADS) {
        float m = -INFINITY;
        for (int k = 0; k < cnt; k++) m = fmaxf(m, al[k * HEADS + tid]);
        float s = 0.f;
        for (int k = 0; k < cnt; k++) { float p = expf(al[k * HEADS + tid] - m); al[k * HEADS + tid] = p; s += p; }
        float inv = 1.f / s;
        for (int k = 0; k < cnt; k++) al[k * HEADS + tid] *= inv;
    }
    __syncthreads();
    for (int o = tid; o < H1DIM; o += blockDim.x) {
        int hd = o >> 8;
        float acc = 0.f;
        for (int k = 0; k < cnt; k++) {
            int sn = edge_src(g_inc[off + k]);
            acc += al[k * HEADS + hd] * g_h1[sn * H1DIM + o];
        }
        g_x1[tnode * H1DIM + o] = fmaxf(acc + b1[o], 0.f);
    }
}

// ---------------- K8: h2 = x1 @ W2T + layer-2 attention scores -------------
__global__ void k_gemm2(const float* __restrict__ a_src,
                        const float* __restrict__ a_dst) {
    int n = blockIdx.x, t = threadIdx.x;     // 256 threads
    int w = t >> 5, lane = t & 31;
    __shared__ __align__(16) float sX[H1DIM];
    __shared__ float lg[OUTD];
    for (int c = t; c < H1DIM; c += 256) sX[c] = g_x1[n * H1DIM + c];
    __syncthreads();
    for (int o = w; o < OUTD; o += 8) {
        float acc = 0.f;
        const float* wr = &g_W2T[o * H1DIM];
        for (int c = lane; c < H1DIM; c += 32)
            acc += sX[c] * wr[c];
#pragma unroll
        for (int s = 16; s; s >>= 1) acc += __shfl_down_sync(0xffffffffu, acc, s);
        if (!lane) { g_h2[n * OUTD + o] = acc; lg[o] = acc; }
    }
    __syncthreads();
    if (t == 0) {
        float s = 0.f, d = 0.f;
        for (int oo = 0; oo < OUTD; oo++) {
            s += lg[oo] * a_src[oo];
            d += lg[oo] * a_dst[oo];
        }
        g_ss2[n] = s; g_ds2[n] = d;
    }
}

// ---------------- K10: GAT2 aggregate -> logits + argmax labels ------------
__global__ void k_gat2(const float* __restrict__ b2, float* __restrict__ out,
                       int out_size) {
    int tnode = blockIdx.x, tid = threadIdx.x;   // block of 32
    int off = g_off[tnode], cnt = g_off[tnode + 1] - off;
    __shared__ float al[E_TOT];
    __shared__ float lg[OUTD];
    for (int k = tid; k < cnt; k += 32) {
        int sn = edge_src(g_inc[off + k]);
        float x = g_ss2[sn] + g_ds2[tnode];
        al[k] = (x >= 0.f) ? x : 0.2f * x;
    }
    __syncthreads();
    if (tid == 0) {
        float m = -INFINITY;
        for (int k = 0; k < cnt; k++) m = fmaxf(m, al[k]);
        float s = 0.f;
        for (int k = 0; k < cnt; k++) { float p = expf(al[k] - m); al[k] = p; s += p; }
        float inv = 1.f / s;
        for (int k = 0; k < cnt; k++) al[k] *= inv;
    }
    __syncthreads();
    for (int o = tid; o < OUTD; o += 32) {
        float acc = 0.f;
        for (int k = 0; k < cnt; k++) {
            int sn = edge_src(g_inc[off + k]);
            acc += al[k] * g_h2[sn * OUTD + o];
        }
        float v = acc + b2[o];
        lg[o] = v;
        out[tnode * OUTD + o] = v;
    }
    __syncthreads();
    if (tid == 0 && out_size >= NN * OUTD + NN) {
        int best = 0;
        float bv = lg[0];
        for (int o = 1; o < OUTD; o++)
            if (lg[o] > bv) { bv = lg[o]; best = o; }
        out[NN * OUTD + tnode] = (float)best;
    }
}

// ---------------------------------------------------------------------------
extern "C" void kernel_launch(void* const* d_in, const int* in_sizes, int n_in,
                              void* d_out, int out_size) {
    const float* features = (const float*)d_in[0];
    const float* boxes    = (const float*)d_in[1];
    const float* W_fc1    = (const float*)d_in[2];
    const float* b_fc1    = (const float*)d_in[3];
    const float* W_fc2    = (const float*)d_in[4];
    const float* b_fc2    = (const float*)d_in[5];
    const float* W1       = (const float*)d_in[6];
    const float* a_src1   = (const float*)d_in[7];
    const float* a_dst1   = (const float*)d_in[8];
    const float* b1       = (const float*)d_in[9];
    const float* W2       = (const float*)d_in[10];
    const float* a_src2   = (const float*)d_in[11];
    const float* a_dst2   = (const float*)d_in[12];
    const float* b2       = (const float*)d_in[13];
    const void*  img_h    = d_in[14];
    const void*  img_w    = d_in[15];
    float* out = (float*)d_out;

    // side stream + events (created once; same GPU work every call)
    static cudaStream_t s1 = nullptr;
    static cudaEvent_t  e0 = nullptr, e1 = nullptr;
    if (!s1) {
        cudaStreamCreateWithFlags(&s1, cudaStreamNonBlocking);
        cudaEventCreateWithFlags(&e0, cudaEventDisableTiming);
        cudaEventCreateWithFlags(&e1, cudaEventDisableTiming);
    }

    // fork: main chain = rel-graph construction; side chain = GAT input GEMM
    cudaEventRecord(e0, 0);
    cudaStreamWaitEvent(s1, e0, 0);

    // main chain (capture-origin stream)
    k_ab<<<dim3(8, 8), 128>>>(features, W_fc1);
    k_rel<<<dim3(4, 32), 128>>>(boxes, W_fc1, b_fc1, W_fc2, b_fc2);
    k_topk_edges<<<1, 1024>>>(W2);

    // side chain
    k_gemm1<<<dim3(16, 8), 128, 0, s1>>>(features, boxes, W1, img_h, img_w);
    k_score1<<<NN, 128, 0, s1>>>(a_src1, a_dst1);

    // join
    cudaEventRecord(e1, s1);
    cudaStreamWaitEvent(0, e1, 0);

    // tail
    k_gat1<<<NN, 256>>>(b1);
    k_gemm2<<<NN, 256>>>(a_src2, a_dst2);
    k_gat2<<<NN, 32>>>(b2, out, out_size);
}

// round 7
// speedup vs baseline: 1.2626x; 1.0251x over previous
#include <cuda_runtime.h>
#include <math.h>

#define NN    256
#define FEATD 1024
#define HIDR  256
#define HEADS 4
#define GCH   256
#define H1DIM 1024   // HEADS*GCH
#define OUTD  21
#define TOPK  3
#define E_TOT (NN*TOPK + NN)   // 1024 edges

// ---------------- scratch (device globals; no allocation allowed) ----------
__device__ __align__(16) float g_A[NN*HIDR];
__device__ __align__(16) float g_B[NN*HIDR];
__device__ __align__(16) float g_rel[NN*NN];
__device__ int   g_off[NN+1];
__device__ int   g_inc[E_TOT];
__device__ __align__(16) float g_h1[NN*H1DIM];
__device__ float g_ss1[NN*HEADS], g_ds1[NN*HEADS];
__device__ __align__(16) float g_x1[NN*H1DIM];
__device__ __align__(16) float g_h2[NN*OUTD];
__device__ float g_ss2[NN], g_ds2[NN];
__device__ __align__(16) float g_W2T[OUTD*H1DIM];   // W2 transposed [o][c]

// edge id -> source node (edges 0..767 are topk from row e/3; 768.. are loops)
__device__ __forceinline__ int edge_src(int e) {
    return (e < NN * TOPK) ? (e / TOPK) : (e - NN * TOPK);
}

// read a scalar that may have been serialized as int32 or float32
__device__ __forceinline__ float read_dim(const void* p) {
    int iv = *(const int*)p;
    if (iv > 0 && iv < 100000) return (float)iv;
    return *(const float*)p;
}

// ====== split-K SGEMM core: 256 thr = 2 halves, each 32x64 tile, K/2 =======
// Each half (128 threads) computes the full 32x64 output tile over its K-half
// in its own smem buffers; caller reduces the two partials.
struct Acc44 { float a[4][4]; };

__device__ __forceinline__ void sgemm_half_32x64(
    const float* __restrict__ Abase, int lda,
    const float* __restrict__ Wbase, int ldw,
    int row0, int col0, int K, Acc44& acc,
    float (*sAT)[36], float (*sW)[64])
{
    int ht = threadIdx.x & 127;
    int half = threadIdx.x >> 7;
    int arow = ht >> 2, akq = ht & 3;        // A loader: 32 rows x 4 k-quads
    int wkr = ht >> 3, wcq = ht & 7;         // W loader: 16 k-rows x 8 col-octs
    int tx4 = (ht & 15) * 4, ty4 = (ht >> 4) * 4;
    int khalf = K >> 1;
    int k0 = half * khalf;
    int KT = khalf >> 4;                     // 16-wide k-tiles per half
    const float* Aptr = Abase + (size_t)(row0 + arow) * lda + k0 + akq * 4;
    const float* Wptr = Wbase + (size_t)(k0 + wkr) * ldw + col0 + wcq * 8;
    float4 pa  = *(const float4*)Aptr;
    float4 pw0 = *(const float4*)Wptr;
    float4 pw1 = *(const float4*)(Wptr + 4);
    for (int kt = 0; kt < KT; kt++) {
        sAT[akq*4+0][arow] = pa.x;
        sAT[akq*4+1][arow] = pa.y;
        sAT[akq*4+2][arow] = pa.z;
        sAT[akq*4+3][arow] = pa.w;
        *(float4*)&sW[wkr][wcq*8]     = pw0;
        *(float4*)&sW[wkr][wcq*8 + 4] = pw1;
        __syncthreads();
        if (kt + 1 < KT) {
            const float* An = Aptr + (kt + 1) * 16;
            const float* Wn = Wptr + (size_t)(kt + 1) * 16 * ldw;
            pa  = *(const float4*)An;
            pw0 = *(const float4*)Wn;
            pw1 = *(const float4*)(Wn + 4);
        }
#pragma unroll
        for (int kk = 0; kk < 16; kk++) {
            float4 a = *(const float4*)&sAT[kk][ty4];
            float4 w = *(const float4*)&sW[kk][tx4];
            acc.a[0][0] += a.x * w.x; acc.a[0][1] += a.x * w.y; acc.a[0][2] += a.x * w.z; acc.a[0][3] += a.x * w.w;
            acc.a[1][0] += a.y * w.x; acc.a[1][1] += a.y * w.y; acc.a[1][2] += a.y * w.z; acc.a[1][3] += a.y * w.w;
            acc.a[2][0] += a.z * w.x; acc.a[2][1] += a.z * w.y; acc.a[2][2] += a.z * w.z; acc.a[2][3] += a.z * w.w;
            acc.a[3][0] += a.w * w.x; acc.a[3][1] += a.w * w.y; acc.a[3][2] += a.w * w.z; acc.a[3][3] += a.w * w.w;
        }
        __syncthreads();
    }
}

// ---------------- K1: combined GEMMs -----------------------------------
// Blocks 0..63   : [g_A | g_B] = F @ W_fc1[0:2048]  (256 x 512)
// Blocks 64..191 : g_h1 = [F | geomn] @ W1          (256 x 1024)
__global__ __launch_bounds__(256, 2)
void k_mm(const float* __restrict__ feat, const float* __restrict__ Wfc1,
          const float* __restrict__ W1, const float* __restrict__ boxes,
          const void* img_h, const void* img_w) {
    __shared__ float sAT[2][16][36];
    __shared__ float sW[2][16][64];
    __shared__ float sRed[128][17];
    int b = blockIdx.x;
    int t = threadIdx.x;
    int half = t >> 7, ht = t & 127;
    int tx4 = (ht & 15) * 4, ty4 = (ht >> 4) * 4;

    const float* W;
    float* dst;
    int row0, colL, ldw;
    bool gemm1 = (b >= 64);
    if (!gemm1) {
        int col0g = (b & 7) * 64;
        row0 = (b >> 3) * 32;
        ldw = HIDR;
        if (col0g < 256) { W = Wfc1;                       dst = g_A; colL = col0g; }
        else             { W = Wfc1 + (size_t)1024 * HIDR; dst = g_B; colL = col0g - 256; }
    } else {
        int i = b - 64;
        colL = (i & 15) * 64;
        row0 = (i >> 4) * 32;
        ldw = H1DIM;
        W = W1;
        dst = g_h1;
    }

    Acc44 acc = {};
    sgemm_half_32x64(feat, FEATD, W, ldw, row0, colL, FEATD, acc, sAT[half], sW[half]);

    // reduce the two K-halves
    if (half == 1) {
#pragma unroll
        for (int u = 0; u < 4; u++)
#pragma unroll
            for (int q = 0; q < 4; q++)
                sRed[ht][u * 4 + q] = acc.a[u][q];
    }
    __syncthreads();
    if (half == 0) {
#pragma unroll
        for (int u = 0; u < 4; u++)
#pragma unroll
            for (int q = 0; q < 4; q++)
                acc.a[u][q] += sRed[ht][u * 4 + q];
        if (gemm1) {
            float fw = read_dim(img_w), fh = read_dim(img_h);
#pragma unroll
            for (int u = 0; u < 4; u++) {
                int n = row0 + ty4 + u;
                float b0 = boxes[n*4+0] / fw, b1 = boxes[n*4+1] / fh;
                float b2 = boxes[n*4+2] / fw, b3 = boxes[n*4+3] / fh;
                float G[4] = { b0, b1, b2 - b0, b3 - b1 };
#pragma unroll
                for (int kk = 0; kk < 4; kk++) {
                    float4 w = *(const float4*)&W1[(size_t)(FEATD + kk) * H1DIM + colL + tx4];
                    acc.a[u][0] += G[kk] * w.x;
                    acc.a[u][1] += G[kk] * w.y;
                    acc.a[u][2] += G[kk] * w.z;
                    acc.a[u][3] += G[kk] * w.w;
                }
            }
        }
#pragma unroll
        for (int u = 0; u < 4; u++) {
            int r = row0 + ty4 + u;
            *(float4*)&dst[(size_t)r * ldw + colL + tx4] =
                make_float4(acc.a[u][0], acc.a[u][1], acc.a[u][2], acc.a[u][3]);
        }
    }
}

// ---------------- K2: rel[i,j] = relu(A[i]+B[j]+bias+geom@Wg) . W_fc2 + b2 -
__global__ void k_rel(const float* __restrict__ boxes,
                      const float* __restrict__ Wfc1,
                      const float* __restrict__ bfc1,
                      const float* __restrict__ Wfc2,
                      const float* __restrict__ bfc2) {
    __shared__ __align__(16) float sAb[8][HIDR];
    __shared__ __align__(16) float sBt[HIDR][68];
    __shared__ __align__(16) float4 sGeo[HIDR];
    __shared__ float sW2[HIDR];
    int t = threadIdx.x;                 // 128
    int il = t >> 4, jg = t & 15, jl = jg * 4;
    int i0 = blockIdx.y * 8, j0 = blockIdx.x * 64;
    const float* Wg = Wfc1 + (size_t)2 * FEATD * HIDR;
    for (int idx = t; idx < 8 * HIDR; idx += 128) {
        int i = idx >> 8, c = idx & 255;
        sAb[i][c] = g_A[(size_t)(i0 + i) * HIDR + c] + bfc1[c];
    }
    for (int idx = t; idx < 64 * HIDR; idx += 128) {
        int j = idx >> 8, c = idx & 255;
        sBt[c][j] = g_B[(size_t)(j0 + j) * HIDR + c];
    }
    for (int c = t; c < HIDR; c += 128) {
        sGeo[c] = make_float4(Wg[c], Wg[HIDR + c], Wg[2 * HIDR + c], Wg[3 * HIDR + c]);
        sW2[c] = Wfc2[c];
    }
    __syncthreads();
    int ig = i0 + il;
    float bi0 = boxes[ig*4+0], bi1 = boxes[ig*4+1], bi2 = boxes[ig*4+2], bi3 = boxes[ig*4+3];
    float4 G[4];
#pragma unroll
    for (int q = 0; q < 4; q++) {
        int jgl = j0 + jl + q;
        G[q] = make_float4(fabsf(bi0 - boxes[jgl*4+0]), fabsf(bi1 - boxes[jgl*4+1]),
                           fabsf(bi2 - boxes[jgl*4+2]), fabsf(bi3 - boxes[jgl*4+3]));
    }
    float acc[4] = {};
#pragma unroll 4
    for (int c = 0; c < HIDR; c++) {
        float  a  = sAb[il][c];
        float4 wg = sGeo[c];
        float  w2 = sW2[c];
        float4 b4 = *(const float4*)&sBt[c][jl];
        float v0 = a + b4.x + G[0].x*wg.x + G[0].y*wg.y + G[0].z*wg.z + G[0].w*wg.w;
        float v1 = a + b4.y + G[1].x*wg.x + G[1].y*wg.y + G[1].z*wg.z + G[1].w*wg.w;
        float v2 = a + b4.z + G[2].x*wg.x + G[2].y*wg.y + G[2].z*wg.z + G[2].w*wg.w;
        float v3 = a + b4.w + G[3].x*wg.x + G[3].y*wg.y + G[3].z*wg.z + G[3].w*wg.w;
        acc[0] += fmaxf(v0, 0.f) * w2;
        acc[1] += fmaxf(v1, 0.f) * w2;
        acc[2] += fmaxf(v2, 0.f) * w2;
        acc[3] += fmaxf(v3, 0.f) * w2;
    }
    float bb = bfc2[0];
#pragma unroll
    for (int q = 0; q < 4; q++)
        g_rel[(size_t)ig * NN + j0 + jl + q] = acc[q] + bb;
}

// ---------------- K3: fused top-k + CSR build (one block, 1024 threads) ----
__global__ void k_topk_edges(const float* __restrict__ W2) {
    int t = threadIdx.x;                 // 0..1023
    int lane = t & 31, w = t >> 5;       // 32 warps
    __shared__ int sTop[NN * TOPK];
    __shared__ int M[32][NN];            // chunk x node counts -> excl. prefixes
    __shared__ int off[NN];
    for (int idx = t; idx < 32 * NN; idx += 1024) ((int*)M)[idx] = 0;
    // ---- top-k ----
    for (int i = w; i < NN; i += 32) {
        float v[8];
#pragma unroll
        for (int q = 0; q < 8; q++) v[q] = g_rel[i * NN + q * 32 + lane];
#pragma unroll
        for (int sel = 0; sel < TOPK + 1; sel++) {
            float bv = -INFINITY; int bi = 0;
#pragma unroll
            for (int q = 0; q < 8; q++) {
                int idx = q * 32 + lane;
                if (v[q] > bv) { bv = v[q]; bi = idx; }
            }
#pragma unroll
            for (int o = 16; o; o >>= 1) {
                float ov = __shfl_down_sync(0xffffffffu, bv, o);
                int   oi = __shfl_down_sync(0xffffffffu, bi, o);
                if (ov > bv || (ov == bv && oi < bi)) { bv = ov; bi = oi; }
            }
            bi = __shfl_sync(0xffffffffu, bi, 0);
            if (sel > 0 && lane == 0) sTop[i * TOPK + sel - 1] = bi;
            if ((bi & 31) == lane) v[bi >> 5] = -INFINITY;
        }
    }
    // ---- W2 transpose side job ----
    for (int idx = t; idx < OUTD * H1DIM; idx += 1024) {
        int o = idx / H1DIM, c = idx - o * H1DIM;
        g_W2T[idx] = W2[c * OUTD + o];
    }
    __syncthreads();
    // ---- CSR build (sort-free, deterministic) ----
    int e = t;
    int tg = (e < NN * TOPK) ? sTop[e] : (e - NN * TOPK);
    unsigned same = __match_any_sync(0xffffffffu, tg);
    int rank = __popc(same & ((1u << lane) - 1u));
    if (rank == 0) M[w][tg] = __popc(same);
    __syncthreads();
    if (t < NN) {
        int run = 0;
#pragma unroll
        for (int cc = 0; cc < 32; cc++) { int v = M[cc][t]; M[cc][t] = run; run += v; }
        off[t] = run;
    }
    __syncthreads();
    for (int s = 1; s < NN; s <<= 1) {
        int v = 0;
        if (t < NN && t >= s) v = off[t - s];
        __syncthreads();
        if (t < NN) off[t] += v;
        __syncthreads();
    }
    if (t < NN) {
        g_off[t + 1] = off[t];
        if (t == 0) g_off[0] = 0;
    }
    __syncthreads();
    int base = (tg == 0) ? 0 : off[tg - 1];
    g_inc[base + M[w][tg] + rank] = e;
}

// ---------------- K6: per-node per-head attention scores (layer 1) ---------
__global__ void k_score1(const float* __restrict__ a_src,
                         const float* __restrict__ a_dst) {
    int n = blockIdx.x;
    int hd = threadIdx.x >> 5, lane = threadIdx.x & 31;
    float s = 0.f, d = 0.f;
    for (int c = lane; c < GCH; c += 32) {
        float hv = g_h1[n * H1DIM + hd * GCH + c];
        s += hv * a_src[hd * GCH + c];
        d += hv * a_dst[hd * GCH + c];
    }
#pragma unroll
    for (int o = 16; o; o >>= 1) {
        s += __shfl_down_sync(0xffffffffu, s, o);
        d += __shfl_down_sync(0xffffffffu, d, o);
    }
    if (!lane) { g_ss1[n * HEADS + hd] = s; g_ds1[n * HEADS + hd] = d; }
}

// ---------------- K7: GAT1 softmax aggregation + bias + relu ---------------
__global__ void k_gat1(const float* __restrict__ b1) {
    int tnode = blockIdx.x, tid = threadIdx.x;
    int off = g_off[tnode], cnt = g_off[tnode + 1] - off;
    __shared__ float al[E_TOT * HEADS];
    for (int idx = tid; idx < cnt * HEADS; idx += blockDim.x) {
        int k = idx >> 2, hd = idx & 3;
        int sn = edge_src(g_inc[off + k]);
        float x = g_ss1[sn * HEADS + hd] + g_ds1[tnode * HEADS + hd];
        al[idx] = (x >= 0.f) ? x : 0.2f * x;   // leaky_relu 0.2
    }
    __syncthreads();
    if (tid < HEADS) {
        float m = -INFINITY;
        for (int k = 0; k < cnt; k++) m = fmaxf(m, al[k * HEADS + tid]);
        float s = 0.f;
        for (int k = 0; k < cnt; k++) { float p = expf(al[k * HEADS + tid] - m); al[k * HEADS + tid] = p; s += p; }
        float inv = 1.f / s;
        for (int k = 0; k < cnt; k++) al[k * HEADS + tid] *= inv;
    }
    __syncthreads();
    for (int o = tid; o < H1DIM; o += blockDim.x) {
        int hd = o >> 8;
        float acc = 0.f;
        for (int k = 0; k < cnt; k++) {
            int sn = edge_src(g_inc[off + k]);
            acc += al[k * HEADS + hd] * g_h1[sn * H1DIM + o];
        }
        g_x1[tnode * H1DIM + o] = fmaxf(acc + b1[o], 0.f);
    }
}

// ---------------- K8: h2 = x1 @ W2T + layer-2 attention scores -------------
__global__ void k_gemm2(const float* __restrict__ a_src,
                        const float* __restrict__ a_dst) {
    int n = blockIdx.x, t = threadIdx.x;     // 256 threads
    int w = t >> 5, lane = t & 31;
    __shared__ __align__(16) float sX[H1DIM];
    __shared__ float lg[OUTD];
    for (int c = t; c < H1DIM; c += 256) sX[c] = g_x1[n * H1DIM + c];
    __syncthreads();
    for (int o = w; o < OUTD; o += 8) {
        float acc = 0.f;
        const float* wr = &g_W2T[o * H1DIM];
        for (int c = lane; c < H1DIM; c += 32)
            acc += sX[c] * wr[c];
#pragma unroll
        for (int s = 16; s; s >>= 1) acc += __shfl_down_sync(0xffffffffu, acc, s);
        if (!lane) { g_h2[n * OUTD + o] = acc; lg[o] = acc; }
    }
    __syncthreads();
    if (t == 0) {
        float s = 0.f, d = 0.f;
        for (int oo = 0; oo < OUTD; oo++) {
            s += lg[oo] * a_src[oo];
            d += lg[oo] * a_dst[oo];
        }
        g_ss2[n] = s; g_ds2[n] = d;
    }
}

// ---------------- K10: GAT2 aggregate -> logits + argmax labels ------------
__global__ void k_gat2(const float* __restrict__ b2, float* __restrict__ out,
                       int out_size) {
    int tnode = blockIdx.x, tid = threadIdx.x;   // block of 32
    int off = g_off[tnode], cnt = g_off[tnode + 1] - off;
    __shared__ float al[E_TOT];
    __shared__ float lg[OUTD];
    for (int k = tid; k < cnt; k += 32) {
        int sn = edge_src(g_inc[off + k]);
        float x = g_ss2[sn] + g_ds2[tnode];
        al[k] = (x >= 0.f) ? x : 0.2f * x;
    }
    __syncthreads();
    if (tid == 0) {
        float m = -INFINITY;
        for (int k = 0; k < cnt; k++) m = fmaxf(m, al[k]);
        float s = 0.f;
        for (int k = 0; k < cnt; k++) { float p = expf(al[k] - m); al[k] = p; s += p; }
        float inv = 1.f / s;
        for (int k = 0; k < cnt; k++) al[k] *= inv;
    }
    __syncthreads();
    for (int o = tid; o < OUTD; o += 32) {
        float acc = 0.f;
        for (int k = 0; k < cnt; k++) {
            int sn = edge_src(g_inc[off + k]);
            acc += al[k] * g_h2[sn * OUTD + o];
        }
        float v = acc + b2[o];
        lg[o] = v;
        out[tnode * OUTD + o] = v;
    }
    __syncthreads();
    if (tid == 0 && out_size >= NN * OUTD + NN) {
        int best = 0;
        float bv = lg[0];
        for (int o = 1; o < OUTD; o++)
            if (lg[o] > bv) { bv = lg[o]; best = o; }
        out[NN * OUTD + tnode] = (float)best;
    }
}

// ---------------------------------------------------------------------------
extern "C" void kernel_launch(void* const* d_in, const int* in_sizes, int n_in,
                              void* d_out, int out_size) {
    const float* features = (const float*)d_in[0];
    const float* boxes    = (const float*)d_in[1];
    const float* W_fc1    = (const float*)d_in[2];
    const float* b_fc1    = (const float*)d_in[3];
    const float* W_fc2    = (const float*)d_in[4];
    const float* b_fc2    = (const float*)d_in[5];
    const float* W1       = (const float*)d_in[6];
    const float* a_src1   = (const float*)d_in[7];
    const float* a_dst1   = (const float*)d_in[8];
    const float* b1       = (const float*)d_in[9];
    const float* W2       = (const float*)d_in[10];
    const float* a_src2   = (const float*)d_in[11];
    const float* a_dst2   = (const float*)d_in[12];
    const float* b2       = (const float*)d_in[13];
    const void*  img_h    = d_in[14];
    const void*  img_w    = d_in[15];
    float* out = (float*)d_out;

    // side stream + events (created once; same GPU work every call)
    static cudaStream_t s1 = nullptr;
    static cudaEvent_t  e0 = nullptr, e1 = nullptr;
    if (!s1) {
        cudaStreamCreateWithFlags(&s1, cudaStreamNonBlocking);
        cudaEventCreateWithFlags(&e0, cudaEventDisableTiming);
        cudaEventCreateWithFlags(&e1, cudaEventDisableTiming);
    }

    // combined GEMMs (A/B for relnet + h1 for GAT) in one wave
    k_mm<<<192, 256>>>(features, W_fc1, W1, boxes, img_h, img_w);

    // fork: main = rel-graph construction; side = GAT1 attention scores
    cudaEventRecord(e0, 0);
    cudaStreamWaitEvent(s1, e0, 0);

    k_rel<<<dim3(4, 32), 128>>>(boxes, W_fc1, b_fc1, W_fc2, b_fc2);
    k_topk_edges<<<1, 1024>>>(W2);

    k_score1<<<NN, 128, 0, s1>>>(a_src1, a_dst1);

    cudaEventRecord(e1, s1);
    cudaStreamWaitEvent(0, e1, 0);

    // tail
    k_gat1<<<NN, 256>>>(b1);
    k_gemm2<<<NN, 256>>>(a_src2, a_dst2);
    k_gat2<<<NN, 32>>>(b2, out, out_size);
}

// round 10
// speedup vs baseline: 1.4479x; 1.1468x over previous
#include <cuda_runtime.h>
#include <math.h>

#define NN    256
#define FEATD 1024
#define HIDR  256
#define HEADS 4
#define GCH   256
#define H1DIM 1024   // HEADS*GCH
#define OUTD  21
#define TOPK  3
#define E_TOT (NN*TOPK + NN)   // 1024 edges

// ---------------- scratch (device globals; no allocation allowed) ----------
__device__ __align__(16) float g_A[NN*HIDR];
__device__ __align__(16) float g_B[NN*HIDR];
__device__ __align__(16) float g_rel[NN*NN];
__device__ int   g_off[NN+1];
__device__ int   g_inc[E_TOT];
__device__ __align__(16) float g_h1[NN*H1DIM];
__device__ float g_ss1[NN*HEADS], g_ds1[NN*HEADS];
__device__ __align__(16) float g_h2[NN*OUTD];
__device__ float g_ss2[NN], g_ds2[NN];
__device__ __align__(16) float g_W2T[OUTD*H1DIM];   // W2 transposed [o][c]

// edge id -> source node (edges 0..767 are topk from row e/3; 768.. are loops)
__device__ __forceinline__ int edge_src(int e) {
    return (e < NN * TOPK) ? (e / TOPK) : (e - NN * TOPK);
}

// read a scalar that may have been serialized as int32 or float32
__device__ __forceinline__ float read_dim(const void* p) {
    int iv = *(const int*)p;
    if (iv > 0 && iv < 100000) return (float)iv;
    return *(const float*)p;
}

// ---------------- K1: combined GEMMs, 4-way split-K ------------------------
// 512 threads = 4 quarters; each quarter computes the 32x64 tile over K/4 in
// its own smem buffers; quarter 0 reduces + epilogue.
// Blocks 0..63   : [g_A | g_B] = F @ W_fc1[0:2048]  (256 x 512)
// Blocks 64..191 : g_h1 = [F | geomn] @ W1          (256 x 1024)
struct Acc44 { float a[4][4]; };

__global__ __launch_bounds__(512, 1)
void k_mm(const float* __restrict__ feat, const float* __restrict__ Wfc1,
          const float* __restrict__ W1, const float* __restrict__ boxes,
          const void* img_h, const void* img_w) {
    __shared__ float sbuf[6600];             // 4x tile sets (6400) / reduction (6528)
    int b = blockIdx.x;
    int t = threadIdx.x;
    int q = t >> 7, ht = t & 127;
    int tx4 = (ht & 15) * 4, ty4 = (ht >> 4) * 4;

    const float* W;
    float* dst;
    int row0, colL, ldw;
    bool gemm1 = (b >= 64);
    if (!gemm1) {
        int col0g = (b & 7) * 64;
        row0 = (b >> 3) * 32;
        ldw = HIDR;
        if (col0g < 256) { W = Wfc1;                       dst = g_A; colL = col0g; }
        else             { W = Wfc1 + (size_t)1024 * HIDR; dst = g_B; colL = col0g - 256; }
    } else {
        int i = b - 64;
        colL = (i & 15) * 64;
        row0 = (i >> 4) * 32;
        ldw = H1DIM;
        W = W1;
        dst = g_h1;
    }

    float* reg = sbuf + q * 1600;
    float (*sAT)[36] = (float (*)[36])reg;
    float (*sW)[64]  = (float (*)[64])(reg + 16 * 36);

    int arow = ht >> 2, akq = ht & 3;
    int wkr  = ht >> 3, wcq = ht & 7;
    int k0 = q * 256;                        // quarter of K=1024
    const float* Aptr = feat + (size_t)(row0 + arow) * FEATD + k0 + akq * 4;
    const float* Wptr = W + (size_t)(k0 + wkr) * ldw + colL + wcq * 8;

    Acc44 acc = {};
    float4 pa  = *(const float4*)Aptr;
    float4 pw0 = *(const float4*)Wptr;
    float4 pw1 = *(const float4*)(Wptr + 4);
#pragma unroll 1
    for (int kt = 0; kt < 16; kt++) {
        sAT[akq*4+0][arow] = pa.x;
        sAT[akq*4+1][arow] = pa.y;
        sAT[akq*4+2][arow] = pa.z;
        sAT[akq*4+3][arow] = pa.w;
        *(float4*)&sW[wkr][wcq*8]     = pw0;
        *(float4*)&sW[wkr][wcq*8 + 4] = pw1;
        __syncthreads();
        if (kt + 1 < 16) {
            const float* An = Aptr + (kt + 1) * 16;
            const float* Wn = Wptr + (size_t)(kt + 1) * 16 * ldw;
            pa  = *(const float4*)An;
            pw0 = *(const float4*)Wn;
            pw1 = *(const float4*)(Wn + 4);
        }
#pragma unroll
        for (int kk = 0; kk < 16; kk++) {
            float4 a = *(const float4*)&sAT[kk][ty4];
            float4 w = *(const float4*)&sW[kk][tx4];
            acc.a[0][0] += a.x * w.x; acc.a[0][1] += a.x * w.y; acc.a[0][2] += a.x * w.z; acc.a[0][3] += a.x * w.w;
            acc.a[1][0] += a.y * w.x; acc.a[1][1] += a.y * w.y; acc.a[1][2] += a.y * w.z; acc.a[1][3] += a.y * w.w;
            acc.a[2][0] += a.z * w.x; acc.a[2][1] += a.z * w.y; acc.a[2][2] += a.z * w.z; acc.a[2][3] += a.z * w.w;
            acc.a[3][0] += a.w * w.x; acc.a[3][1] += a.w * w.y; acc.a[3][2] += a.w * w.z; acc.a[3][3] += a.w * w.w;
        }
        __syncthreads();
    }

    // reduction: quarters 1..3 dump accs (stride 17 -> conflict-free), q0 sums
    if (q > 0) {
        float* rb = sbuf + (q - 1) * 2176 + ht * 17;
#pragma unroll
        for (int u = 0; u < 4; u++)
#pragma unroll
            for (int j = 0; j < 4; j++)
                rb[u * 4 + j] = acc.a[u][j];
    }
    __syncthreads();
    if (q == 0) {
#pragma unroll
        for (int r = 0; r < 3; r++) {
            float* rb = sbuf + r * 2176 + ht * 17;
#pragma unroll
            for (int u = 0; u < 4; u++)
#pragma unroll
                for (int j = 0; j < 4; j++)
                    acc.a[u][j] += rb[u * 4 + j];
        }
        if (gemm1) {
            float fw = read_dim(img_w), fh = read_dim(img_h);
#pragma unroll
            for (int u = 0; u < 4; u++) {
                int n = row0 + ty4 + u;
                float b0 = boxes[n*4+0] / fw, b1 = boxes[n*4+1] / fh;
                float b2 = boxes[n*4+2] / fw, b3 = boxes[n*4+3] / fh;
                float G[4] = { b0, b1, b2 - b0, b3 - b1 };
#pragma unroll
                for (int kk = 0; kk < 4; kk++) {
                    float4 w = *(const float4*)&W1[(size_t)(FEATD + kk) * H1DIM + colL + tx4];
                    acc.a[u][0] += G[kk] * w.x;
                    acc.a[u][1] += G[kk] * w.y;
                    acc.a[u][2] += G[kk] * w.z;
                    acc.a[u][3] += G[kk] * w.w;
                }
            }
        }
#pragma unroll
        for (int u = 0; u < 4; u++) {
            int r = row0 + ty4 + u;
            *(float4*)&dst[(size_t)r * ldw + colL + tx4] =
                make_float4(acc.a[u][0], acc.a[u][1], acc.a[u][2], acc.a[u][3]);
        }
    }
}

// ---------------- K2: rel[i,j] = relu(A[i]+B[j]+bias+geom@Wg) . W_fc2 + b2 -
__global__ void k_rel(const float* __restrict__ boxes,
                      const float* __restrict__ Wfc1,
                      const float* __restrict__ bfc1,
                      const float* __restrict__ Wfc2,
                      const float* __restrict__ bfc2) {
    __shared__ __align__(16) float sAb[8][HIDR];
    __shared__ __align__(16) float sBt[HIDR][68];
    __shared__ __align__(16) float4 sGeo[HIDR];
    __shared__ float sW2[HIDR];
    int t = threadIdx.x;                 // 128
    int il = t >> 4, jg = t & 15, jl = jg * 4;
    int i0 = blockIdx.y * 8, j0 = blockIdx.x * 64;
    const float* Wg = Wfc1 + (size_t)2 * FEATD * HIDR;
    for (int idx = t; idx < 8 * HIDR; idx += 128) {
        int i = idx >> 8, c = idx & 255;
        sAb[i][c] = g_A[(size_t)(i0 + i) * HIDR + c] + bfc1[c];
    }
    for (int idx = t; idx < 64 * HIDR; idx += 128) {
        int j = idx >> 8, c = idx & 255;
        sBt[c][j] = g_B[(size_t)(j0 + j) * HIDR + c];
    }
    for (int c = t; c < HIDR; c += 128) {
        sGeo[c] = make_float4(Wg[c], Wg[HIDR + c], Wg[2 * HIDR + c], Wg[3 * HIDR + c]);
        sW2[c] = Wfc2[c];
    }
    __syncthreads();
    int ig = i0 + il;
    float bi0 = boxes[ig*4+0], bi1 = boxes[ig*4+1], bi2 = boxes[ig*4+2], bi3 = boxes[ig*4+3];
    float4 G[4];
#pragma unroll
    for (int q = 0; q < 4; q++) {
        int jgl = j0 + jl + q;
        G[q] = make_float4(fabsf(bi0 - boxes[jgl*4+0]), fabsf(bi1 - boxes[jgl*4+1]),
                           fabsf(bi2 - boxes[jgl*4+2]), fabsf(bi3 - boxes[jgl*4+3]));
    }
    float acc[4] = {};
#pragma unroll 4
    for (int c = 0; c < HIDR; c++) {
        float  a  = sAb[il][c];
        float4 wg = sGeo[c];
        float  w2 = sW2[c];
        float4 b4 = *(const float4*)&sBt[c][jl];
        float v0 = a + b4.x + G[0].x*wg.x + G[0].y*wg.y + G[0].z*wg.z + G[0].w*wg.w;
        float v1 = a + b4.y + G[1].x*wg.x + G[1].y*wg.y + G[1].z*wg.z + G[1].w*wg.w;
        float v2 = a + b4.z + G[2].x*wg.x + G[2].y*wg.y + G[2].z*wg.z + G[2].w*wg.w;
        float v3 = a + b4.w + G[3].x*wg.x + G[3].y*wg.y + G[3].z*wg.z + G[3].w*wg.w;
        acc[0] += fmaxf(v0, 0.f) * w2;
        acc[1] += fmaxf(v1, 0.f) * w2;
        acc[2] += fmaxf(v2, 0.f) * w2;
        acc[3] += fmaxf(v3, 0.f) * w2;
    }
    float bb = bfc2[0];
#pragma unroll
    for (int q = 0; q < 4; q++)
        g_rel[(size_t)ig * NN + j0 + jl + q] = acc[q] + bb;
}

// ---------------- K3: block 0 = topk + CSR + W2T; blocks 1..32 = score1 ----
__global__ void k_topk_score(const float* __restrict__ W2,
                             const float* __restrict__ a_src,
                             const float* __restrict__ a_dst) {
    int t = threadIdx.x;                 // 1024
    int lane = t & 31, w = t >> 5;
    if (blockIdx.x > 0) {
        // ---- score1: 8 nodes per block, 128 threads per node ----
        int n = (blockIdx.x - 1) * 8 + (t >> 7);
        int wt = t & 127;
        int hd = wt >> 5;
        float s = 0.f, d = 0.f;
        const float* hr = &g_h1[(size_t)n * H1DIM + hd * GCH];
        for (int c = lane; c < GCH; c += 32) {
            float hv = hr[c];
            s += hv * a_src[hd * GCH + c];
            d += hv * a_dst[hd * GCH + c];
        }
#pragma unroll
        for (int o = 16; o; o >>= 1) {
            s += __shfl_down_sync(0xffffffffu, s, o);
            d += __shfl_down_sync(0xffffffffu, d, o);
        }
        if (!lane) { g_ss1[n * HEADS + hd] = s; g_ds1[n * HEADS + hd] = d; }
        return;
    }
    // ---- block 0: topk + CSR + W2T ----
    __shared__ int sTop[NN * TOPK];
    __shared__ int M[32][NN];
    __shared__ int off[NN];
    for (int idx = t; idx < 32 * NN; idx += 1024) ((int*)M)[idx] = 0;
    for (int i = w; i < NN; i += 32) {
        float v[8];
#pragma unroll
        for (int q = 0; q < 8; q++) v[q] = g_rel[i * NN + q * 32 + lane];
#pragma unroll
        for (int sel = 0; sel < TOPK + 1; sel++) {
            float bv = -INFINITY; int bi = 0;
#pragma unroll
            for (int q = 0; q < 8; q++) {
                int idx = q * 32 + lane;
                if (v[q] > bv) { bv = v[q]; bi = idx; }
            }
#pragma unroll
            for (int o = 16; o; o >>= 1) {
                float ov = __shfl_down_sync(0xffffffffu, bv, o);
                int   oi = __shfl_down_sync(0xffffffffu, bi, o);
                if (ov > bv || (ov == bv && oi < bi)) { bv = ov; bi = oi; }
            }
            bi = __shfl_sync(0xffffffffu, bi, 0);
            if (sel > 0 && lane == 0) sTop[i * TOPK + sel - 1] = bi;
            if ((bi & 31) == lane) v[bi >> 5] = -INFINITY;
        }
    }
    for (int idx = t; idx < OUTD * H1DIM; idx += 1024) {
        int o = idx / H1DIM, c = idx - o * H1DIM;
        g_W2T[idx] = W2[c * OUTD + o];
    }
    __syncthreads();
    int e = t;
    int tg = (e < NN * TOPK) ? sTop[e] : (e - NN * TOPK);
    unsigned same = __match_any_sync(0xffffffffu, tg);
    int rank = __popc(same & ((1u << lane) - 1u));
    if (rank == 0) M[w][tg] = __popc(same);
    __syncthreads();
    if (t < NN) {
        int run = 0;
#pragma unroll
        for (int cc = 0; cc < 32; cc++) { int v = M[cc][t]; M[cc][t] = run; run += v; }
        off[t] = run;
    }
    __syncthreads();
    for (int s = 1; s < NN; s <<= 1) {
        int v = 0;
        if (t < NN && t >= s) v = off[t - s];
        __syncthreads();
        if (t < NN) off[t] += v;
        __syncthreads();
    }
    if (t < NN) {
        g_off[t + 1] = off[t];
        if (t == 0) g_off[0] = 0;
    }
    __syncthreads();
    int base = (tg == 0) ? 0 : off[tg - 1];
    g_inc[base + M[w][tg] + rank] = e;
}

// ---------------- K4: fused GAT1 aggregation + gemm2 + scores2 -------------
__global__ void k_gat1f(const float* __restrict__ b1,
                        const float* __restrict__ a_src2,
                        const float* __restrict__ a_dst2) {
    int tnode = blockIdx.x, tid = threadIdx.x;   // 256 threads
    int w = tid >> 5, lane = tid & 31;
    int off = g_off[tnode], cnt = g_off[tnode + 1] - off;
    __shared__ int   sSrc[E_TOT];
    __shared__ float al[E_TOT * HEADS];
    __shared__ __align__(16) float sX[H1DIM];
    __shared__ float lg[OUTD];
    for (int k = tid; k < cnt; k += 256) sSrc[k] = edge_src(g_inc[off + k]);
    __syncthreads();
    for (int idx = tid; idx < cnt * HEADS; idx += 256) {
        int k = idx >> 2, hd = idx & 3;
        float x = g_ss1[sSrc[k] * HEADS + hd] + g_ds1[tnode * HEADS + hd];
        al[idx] = (x >= 0.f) ? x : 0.2f * x;   // leaky_relu 0.2
    }
    __syncthreads();
    // warp-parallel softmax per head
    if (w < HEADS) {
        float m = -INFINITY;
        for (int k = lane; k < cnt; k += 32) m = fmaxf(m, al[k * HEADS + w]);
#pragma unroll
        for (int o = 16; o; o >>= 1) m = fmaxf(m, __shfl_xor_sync(0xffffffffu, m, o));
        float s = 0.f;
        for (int k = lane; k < cnt; k += 32) {
            float p = expf(al[k * HEADS + w] - m);
            al[k * HEADS + w] = p;
            s += p;
        }
#pragma unroll
        for (int o = 16; o; o >>= 1) s += __shfl_xor_sync(0xffffffffu, s, o);
        float inv = 1.f / s;
        for (int k = lane; k < cnt; k += 32) al[k * HEADS + w] *= inv;
    }
    __syncthreads();
    // aggregation: thread owns 4 consecutive outputs
    {
        int o4 = tid * 4;
        int hd = o4 >> 8;
        float ax = 0.f, ay = 0.f, az = 0.f, aw = 0.f;
#pragma unroll 2
        for (int k = 0; k < cnt; k++) {
            float a = al[k * HEADS + hd];
            float4 h = *(const float4*)&g_h1[(size_t)sSrc[k] * H1DIM + o4];
            ax += a * h.x; ay += a * h.y; az += a * h.z; aw += a * h.w;
        }
        float4 bb = *(const float4*)&b1[o4];
        *(float4*)&sX[o4] = make_float4(fmaxf(ax + bb.x, 0.f), fmaxf(ay + bb.y, 0.f),
                                        fmaxf(az + bb.z, 0.f), fmaxf(aw + bb.w, 0.f));
    }
    __syncthreads();
    // gemm2: h2 row = sX @ W2T, warp per output
    for (int o = w; o < OUTD; o += 8) {
        const float* wr = &g_W2T[o * H1DIM];
        float s = 0.f;
        for (int c = lane * 4; c < H1DIM; c += 128) {
            float4 xv = *(const float4*)&sX[c];
            float4 wv = *(const float4*)&wr[c];
            s += xv.x * wv.x + xv.y * wv.y + xv.z * wv.z + xv.w * wv.w;
        }
#pragma unroll
        for (int o2 = 16; o2; o2 >>= 1) s += __shfl_down_sync(0xffffffffu, s, o2);
        if (!lane) { g_h2[tnode * OUTD + o] = s; lg[o] = s; }
    }
    __syncthreads();
    if (tid == 0) {
        float s = 0.f, d = 0.f;
        for (int oo = 0; oo < OUTD; oo++) {
            s += lg[oo] * a_src2[oo];
            d += lg[oo] * a_dst2[oo];
        }
        g_ss2[tnode] = s; g_ds2[tnode] = d;
    }
}

// ---------------- K5: GAT2 aggregate -> logits + argmax labels -------------
__global__ void k_gat2(const float* __restrict__ b2, float* __restrict__ out,
                       int out_size) {
    int tnode = blockIdx.x, tid = threadIdx.x;   // block of 32
    int off = g_off[tnode], cnt = g_off[tnode + 1] - off;
    __shared__ float al[E_TOT];
    __shared__ float lg[OUTD];
    for (int k = tid; k < cnt; k += 32) {
        int sn = edge_src(g_inc[off + k]);
        float x = g_ss2[sn] + g_ds2[tnode];
        al[k] = (x >= 0.f) ? x : 0.2f * x;
    }
    __syncwarp();
    // warp-parallel softmax
    {
        float m = -INFINITY;
        for (int k = tid; k < cnt; k += 32) m = fmaxf(m, al[k]);
#pragma unroll
        for (int o = 16; o; o >>= 1) m = fmaxf(m, __shfl_xor_sync(0xffffffffu, m, o));
        float s = 0.f;
        for (int k = tid; k < cnt; k += 32) { float p = expf(al[k] - m); al[k] = p; s += p; }
#pragma unroll
        for (int o = 16; o; o >>= 1) s += __shfl_xor_sync(0xffffffffu, s, o);
        float inv = 1.f / s;
        for (int k = tid; k < cnt; k += 32) al[k] *= inv;
    }
    __syncwarp();
    for (int o = tid; o < OUTD; o += 32) {
        float acc = 0.f;
        for (int k = 0; k < cnt; k++) {
            int sn = edge_src(g_inc[off + k]);
            acc += al[k] * g_h2[sn * OUTD + o];
        }
        float v = acc + b2[o];
        lg[o] = v;
        out[tnode * OUTD + o] = v;
    }
    __syncwarp();
    if (tid == 0 && out_size >= NN * OUTD + NN) {
        int best = 0;
        float bv = lg[0];
        for (int o = 1; o < OUTD; o++)
            if (lg[o] > bv) { bv = lg[o]; best = o; }
        out[NN * OUTD + tnode] = (float)best;
    }
}

// ---------------------------------------------------------------------------
extern "C" void kernel_launch(void* const* d_in, const int* in_sizes, int n_in,
                              void* d_out, int out_size) {
    const float* features = (const float*)d_in[0];
    const float* boxes    = (const float*)d_in[1];
    const float* W_fc1    = (const float*)d_in[2];
    const float* b_fc1    = (const float*)d_in[3];
    const float* W_fc2    = (const float*)d_in[4];
    const float* b_fc2    = (const float*)d_in[5];
    const float* W1       = (const float*)d_in[6];
    const float* a_src1   = (const float*)d_in[7];
    const float* a_dst1   = (const float*)d_in[8];
    const float* b1       = (const float*)d_in[9];
    const float* W2       = (const float*)d_in[10];
    const float* a_src2   = (const float*)d_in[11];
    const float* a_dst2   = (const float*)d_in[12];
    const float* b2       = (const float*)d_in[13];
    const void*  img_h    = d_in[14];
    const void*  img_w    = d_in[15];
    float* out = (float*)d_out;

    k_mm<<<192, 512>>>(features, W_fc1, W1, boxes, img_h, img_w);
    k_rel<<<dim3(4, 32), 128>>>(boxes, W_fc1, b_fc1, W_fc2, b_fc2);
    k_topk_score<<<33, 1024>>>(W2, a_src1, a_dst1);
    k_gat1f<<<NN, 256>>>(b1, a_src2, a_dst2);
    k_gat2<<<NN, 32>>>(b2, out, out_size);
}

// round 13
// speedup vs baseline: 1.5110x; 1.0436x over previous
#include <cuda_runtime.h>
#include <math.h>

#define NN    256
#define FEATD 1024
#define HIDR  256
#define HEADS 4
#define GCH   256
#define H1DIM 1024   // HEADS*GCH
#define OUTD  21
#define TOPK  3
#define E_TOT (NN*TOPK + NN)   // 1024 edges

// ---------------- scratch (device globals; no allocation allowed) ----------
__device__ __align__(16) float g_A[NN*HIDR];
__device__ __align__(16) float g_B[NN*HIDR];
__device__ __align__(16) float g_rel[NN*NN];
__device__ int   g_off[NN+1];
__device__ int   g_inc[E_TOT];
__device__ __align__(16) float g_h1[NN*H1DIM];
__device__ float g_ss1[NN*HEADS], g_ds1[NN*HEADS];
__device__ __align__(16) float g_h2[NN*OUTD];
__device__ float g_ss2[NN], g_ds2[NN];
__device__ __align__(16) float g_W2T[OUTD*H1DIM];   // W2 transposed [o][c]

// edge id -> source node (edges 0..767 are topk from row e/3; 768.. are loops)
__device__ __forceinline__ int edge_src(int e) {
    return (e < NN * TOPK) ? (e / TOPK) : (e - NN * TOPK);
}

// read a scalar that may have been serialized as int32 or float32
__device__ __forceinline__ float read_dim(const void* p) {
    int iv = *(const int*)p;
    if (iv > 0 && iv < 100000) return (float)iv;
    return *(const float*)p;
}

// ---------------- K1: combined GEMMs, 4-way split-K ------------------------
struct Acc44 { float a[4][4]; };

__global__ __launch_bounds__(512, 1)
void k_mm(const float* __restrict__ feat, const float* __restrict__ Wfc1,
          const float* __restrict__ W1, const float* __restrict__ boxes,
          const void* img_h, const void* img_w) {
    __shared__ float sbuf[6600];             // 4x tile sets (6400) / reduction (6528)
    int b = blockIdx.x;
    int t = threadIdx.x;
    int q = t >> 7, ht = t & 127;
    int tx4 = (ht & 15) * 4, ty4 = (ht >> 4) * 4;

    const float* W;
    float* dst;
    int row0, colL, ldw;
    bool gemm1 = (b >= 64);
    if (!gemm1) {
        int col0g = (b & 7) * 64;
        row0 = (b >> 3) * 32;
        ldw = HIDR;
        if (col0g < 256) { W = Wfc1;                       dst = g_A; colL = col0g; }
        else             { W = Wfc1 + (size_t)1024 * HIDR; dst = g_B; colL = col0g - 256; }
    } else {
        int i = b - 64;
        colL = (i & 15) * 64;
        row0 = (i >> 4) * 32;
        ldw = H1DIM;
        W = W1;
        dst = g_h1;
    }

    float* reg = sbuf + q * 1600;
    float (*sAT)[36] = (float (*)[36])reg;
    float (*sW)[64]  = (float (*)[64])(reg + 16 * 36);

    int arow = ht >> 2, akq = ht & 3;
    int wkr  = ht >> 3, wcq = ht & 7;
    int k0 = q * 256;                        // quarter of K=1024
    const float* Aptr = feat + (size_t)(row0 + arow) * FEATD + k0 + akq * 4;
    const float* Wptr = W + (size_t)(k0 + wkr) * ldw + colL + wcq * 8;

    Acc44 acc = {};
    float4 pa  = *(const float4*)Aptr;
    float4 pw0 = *(const float4*)Wptr;
    float4 pw1 = *(const float4*)(Wptr + 4);
#pragma unroll 1
    for (int kt = 0; kt < 16; kt++) {
        sAT[akq*4+0][arow] = pa.x;
        sAT[akq*4+1][arow] = pa.y;
        sAT[akq*4+2][arow] = pa.z;
        sAT[akq*4+3][arow] = pa.w;
        *(float4*)&sW[wkr][wcq*8]     = pw0;
        *(float4*)&sW[wkr][wcq*8 + 4] = pw1;
        __syncthreads();
        if (kt + 1 < 16) {
            const float* An = Aptr + (kt + 1) * 16;
            const float* Wn = Wptr + (size_t)(kt + 1) * 16 * ldw;
            pa  = *(const float4*)An;
            pw0 = *(const float4*)Wn;
            pw1 = *(const float4*)(Wn + 4);
        }
#pragma unroll
        for (int kk = 0; kk < 16; kk++) {
            float4 a = *(const float4*)&sAT[kk][ty4];
            float4 w = *(const float4*)&sW[kk][tx4];
            acc.a[0][0] += a.x * w.x; acc.a[0][1] += a.x * w.y; acc.a[0][2] += a.x * w.z; acc.a[0][3] += a.x * w.w;
            acc.a[1][0] += a.y * w.x; acc.a[1][1] += a.y * w.y; acc.a[1][2] += a.y * w.z; acc.a[1][3] += a.y * w.w;
            acc.a[2][0] += a.z * w.x; acc.a[2][1] += a.z * w.y; acc.a[2][2] += a.z * w.z; acc.a[2][3] += a.z * w.w;
            acc.a[3][0] += a.w * w.x; acc.a[3][1] += a.w * w.y; acc.a[3][2] += a.w * w.z; acc.a[3][3] += a.w * w.w;
        }
        __syncthreads();
    }

    // reduction: quarters 1..3 dump accs (stride 17 -> conflict-free), q0 sums
    if (q > 0) {
        float* rb = sbuf + (q - 1) * 2176 + ht * 17;
#pragma unroll
        for (int u = 0; u < 4; u++)
#pragma unroll
            for (int j = 0; j < 4; j++)
                rb[u * 4 + j] = acc.a[u][j];
    }
    __syncthreads();
    if (q == 0) {
#pragma unroll
        for (int r = 0; r < 3; r++) {
            float* rb = sbuf + r * 2176 + ht * 17;
#pragma unroll
            for (int u = 0; u < 4; u++)
#pragma unroll
                for (int j = 0; j < 4; j++)
                    acc.a[u][j] += rb[u * 4 + j];
        }
        if (gemm1) {
            float fw = read_dim(img_w), fh = read_dim(img_h);
#pragma unroll
            for (int u = 0; u < 4; u++) {
                int n = row0 + ty4 + u;
                float b0 = boxes[n*4+0] / fw, b1 = boxes[n*4+1] / fh;
                float b2 = boxes[n*4+2] / fw, b3 = boxes[n*4+3] / fh;
                float G[4] = { b0, b1, b2 - b0, b3 - b1 };
#pragma unroll
                for (int kk = 0; kk < 4; kk++) {
                    float4 w = *(const float4*)&W1[(size_t)(FEATD + kk) * H1DIM + colL + tx4];
                    acc.a[u][0] += G[kk] * w.x;
                    acc.a[u][1] += G[kk] * w.y;
                    acc.a[u][2] += G[kk] * w.z;
                    acc.a[u][3] += G[kk] * w.w;
                }
            }
        }
#pragma unroll
        for (int u = 0; u < 4; u++) {
            int r = row0 + ty4 + u;
            *(float4*)&dst[(size_t)r * ldw + colL + tx4] =
                make_float4(acc.a[u][0], acc.a[u][1], acc.a[u][2], acc.a[u][3]);
        }
    }
}

// ---------------- K2: rel[i,j] = relu(A[i]+B[j]+bias+geom@Wg) . W_fc2 + b2 -
__global__ void k_rel(const float* __restrict__ boxes,
                      const float* __restrict__ Wfc1,
                      const float* __restrict__ bfc1,
                      const float* __restrict__ Wfc2,
                      const float* __restrict__ bfc2) {
    __shared__ __align__(16) float sAb[8][HIDR];
    __shared__ __align__(16) float sBt[HIDR][68];
    __shared__ __align__(16) float4 sGeo[HIDR];
    __shared__ float sW2[HIDR];
    int t = threadIdx.x;                 // 128
    int il = t >> 4, jg = t & 15, jl = jg * 4;
    int i0 = blockIdx.y * 8, j0 = blockIdx.x * 64;
    const float* Wg = Wfc1 + (size_t)2 * FEATD * HIDR;
    for (int idx = t; idx < 8 * HIDR; idx += 128) {
        int i = idx >> 8, c = idx & 255;
        sAb[i][c] = g_A[(size_t)(i0 + i) * HIDR + c] + bfc1[c];
    }
    for (int idx = t; idx < 64 * HIDR; idx += 128) {
        int j = idx >> 8, c = idx & 255;
        sBt[c][j] = g_B[(size_t)(j0 + j) * HIDR + c];
    }
    for (int c = t; c < HIDR; c += 128) {
        sGeo[c] = make_float4(Wg[c], Wg[HIDR + c], Wg[2 * HIDR + c], Wg[3 * HIDR + c]);
        sW2[c] = Wfc2[c];
    }
    __syncthreads();
    int ig = i0 + il;
    float bi0 = boxes[ig*4+0], bi1 = boxes[ig*4+1], bi2 = boxes[ig*4+2], bi3 = boxes[ig*4+3];
    float4 G[4];
#pragma unroll
    for (int q = 0; q < 4; q++) {
        int jgl = j0 + jl + q;
        G[q] = make_float4(fabsf(bi0 - boxes[jgl*4+0]), fabsf(bi1 - boxes[jgl*4+1]),
                           fabsf(bi2 - boxes[jgl*4+2]), fabsf(bi3 - boxes[jgl*4+3]));
    }
    float acc[4] = {};
#pragma unroll 4
    for (int c = 0; c < HIDR; c++) {
        float  a  = sAb[il][c];
        float4 wg = sGeo[c];
        float  w2 = sW2[c];
        float4 b4 = *(const float4*)&sBt[c][jl];
        float v0 = a + b4.x + G[0].x*wg.x + G[0].y*wg.y + G[0].z*wg.z + G[0].w*wg.w;
        float v1 = a + b4.y + G[1].x*wg.x + G[1].y*wg.y + G[1].z*wg.z + G[1].w*wg.w;
        float v2 = a + b4.z + G[2].x*wg.x + G[2].y*wg.y + G[2].z*wg.z + G[2].w*wg.w;
        float v3 = a + b4.w + G[3].x*wg.x + G[3].y*wg.y + G[3].z*wg.z + G[3].w*wg.w;
        acc[0] += fmaxf(v0, 0.f) * w2;
        acc[1] += fmaxf(v1, 0.f) * w2;
        acc[2] += fmaxf(v2, 0.f) * w2;
        acc[3] += fmaxf(v3, 0.f) * w2;
    }
    float bb = bfc2[0];
#pragma unroll
    for (int q = 0; q < 4; q++)
        g_rel[(size_t)ig * NN + j0 + jl + q] = acc[q] + bb;
}

// ---------------- K3: block 0 = topk + CSR + W2T; blocks 1..32 = score1 ----
__global__ void k_topk_score(const float* __restrict__ W2,
                             const float* __restrict__ a_src,
                             const float* __restrict__ a_dst) {
    int t = threadIdx.x;                 // 1024
    int lane = t & 31, w = t >> 5;
    if (blockIdx.x > 0) {
        // ---- score1: 8 nodes per block, 128 threads per node ----
        int n = (blockIdx.x - 1) * 8 + (t >> 7);
        int wt = t & 127;
        int hd = wt >> 5;
        float s = 0.f, d = 0.f;
        const float* hr = &g_h1[(size_t)n * H1DIM + hd * GCH];
        for (int c = lane; c < GCH; c += 32) {
            float hv = hr[c];
            s += hv * a_src[hd * GCH + c];
            d += hv * a_dst[hd * GCH + c];
        }
#pragma unroll
        for (int o = 16; o; o >>= 1) {
            s += __shfl_down_sync(0xffffffffu, s, o);
            d += __shfl_down_sync(0xffffffffu, d, o);
        }
        if (!lane) { g_ss1[n * HEADS + hd] = s; g_ds1[n * HEADS + hd] = d; }
        return;
    }
    // ---- block 0: topk + CSR + W2T ----
    __shared__ int sTop[NN * TOPK];
    __shared__ int M[32][NN];
    __shared__ int off[NN];
    for (int idx = t; idx < 32 * NN; idx += 1024) ((int*)M)[idx] = 0;
    for (int i = w; i < NN; i += 32) {
        float v[8];
#pragma unroll
        for (int q = 0; q < 8; q++) v[q] = g_rel[i * NN + q * 32 + lane];
#pragma unroll
        for (int sel = 0; sel < TOPK + 1; sel++) {
            float bv = -INFINITY; int bi = 0;
#pragma unroll
            for (int q = 0; q < 8; q++) {
                int idx = q * 32 + lane;
                if (v[q] > bv) { bv = v[q]; bi = idx; }
            }
#pragma unroll
            for (int o = 16; o; o >>= 1) {
                float ov = __shfl_down_sync(0xffffffffu, bv, o);
                int   oi = __shfl_down_sync(0xffffffffu, bi, o);
                if (ov > bv || (ov == bv && oi < bi)) { bv = ov; bi = oi; }
            }
            bi = __shfl_sync(0xffffffffu, bi, 0);
            if (sel > 0 && lane == 0) sTop[i * TOPK + sel - 1] = bi;
            if ((bi & 31) == lane) v[bi >> 5] = -INFINITY;
        }
    }
    for (int idx = t; idx < OUTD * H1DIM; idx += 1024) {
        int o = idx / H1DIM, c = idx - o * H1DIM;
        g_W2T[idx] = W2[c * OUTD + o];
    }
    __syncthreads();
    int e = t;
    int tg = (e < NN * TOPK) ? sTop[e] : (e - NN * TOPK);
    unsigned same = __match_any_sync(0xffffffffu, tg);
    int rank = __popc(same & ((1u << lane) - 1u));
    if (rank == 0) M[w][tg] = __popc(same);
    __syncthreads();
    if (t < NN) {
        int run = 0;
#pragma unroll
        for (int cc = 0; cc < 32; cc++) { int v = M[cc][t]; M[cc][t] = run; run += v; }
        off[t] = run;
    }
    __syncthreads();
    for (int s = 1; s < NN; s <<= 1) {
        int v = 0;
        if (t < NN && t >= s) v = off[t - s];
        __syncthreads();
        if (t < NN) off[t] += v;
        __syncthreads();
    }
    if (t < NN) {
        g_off[t + 1] = off[t];
        if (t == 0) g_off[0] = 0;
    }
    __syncthreads();
    int base = (tg == 0) ? 0 : off[tg - 1];
    g_inc[base + M[w][tg] + rank] = e;
}

// ---------------- K4: fused GAT1 aggregation + gemm2 + scores2 -------------
__global__ void k_gat1f(const float* __restrict__ b1,
                        const float* __restrict__ a_src2,
                        const float* __restrict__ a_dst2) {
    int tnode = blockIdx.x, tid = threadIdx.x;   // 256 threads
    int w = tid >> 5, lane = tid & 31;
    int off = g_off[tnode], cnt = g_off[tnode + 1] - off;
    __shared__ int   sSrc[E_TOT];
    __shared__ float al[E_TOT * HEADS];
    __shared__ __align__(16) float sX[H1DIM];
    __shared__ float lg[OUTD];
    for (int k = tid; k < cnt; k += 256) sSrc[k] = edge_src(g_inc[off + k]);
    __syncthreads();
    for (int idx = tid; idx < cnt * HEADS; idx += 256) {
        int k = idx >> 2, hd = idx & 3;
        float x = g_ss1[sSrc[k] * HEADS + hd] + g_ds1[tnode * HEADS + hd];
        al[idx] = (x >= 0.f) ? x : 0.2f * x;   // leaky_relu 0.2
    }
    __syncthreads();
    // warp-parallel softmax per head
    if (w < HEADS) {
        float m = -INFINITY;
        for (int k = lane; k < cnt; k += 32) m = fmaxf(m, al[k * HEADS + w]);
#pragma unroll
        for (int o = 16; o; o >>= 1) m = fmaxf(m, __shfl_xor_sync(0xffffffffu, m, o));
        float s = 0.f;
        for (int k = lane; k < cnt; k += 32) {
            float p = expf(al[k * HEADS + w] - m);
            al[k * HEADS + w] = p;
            s += p;
        }
#pragma unroll
        for (int o = 16; o; o >>= 1) s += __shfl_xor_sync(0xffffffffu, s, o);
        float inv = 1.f / s;
        for (int k = lane; k < cnt; k += 32) al[k * HEADS + w] *= inv;
    }
    __syncthreads();
    // aggregation: thread owns 4 consecutive outputs; unroll-by-4 for MLP
    {
        int o4 = tid * 4;
        int hd = o4 >> 8;
        float ax = 0.f, ay = 0.f, az = 0.f, aw = 0.f;
        int k = 0;
        for (; k + 4 <= cnt; k += 4) {
            float a0 = al[(k+0) * HEADS + hd];
            float a1 = al[(k+1) * HEADS + hd];
            float a2 = al[(k+2) * HEADS + hd];
            float a3 = al[(k+3) * HEADS + hd];
            const float4 h0 = *(const float4*)&g_h1[(size_t)sSrc[k+0] * H1DIM + o4];
            const float4 h1 = *(const float4*)&g_h1[(size_t)sSrc[k+1] * H1DIM + o4];
            const float4 h2 = *(const float4*)&g_h1[(size_t)sSrc[k+2] * H1DIM + o4];
            const float4 h3 = *(const float4*)&g_h1[(size_t)sSrc[k+3] * H1DIM + o4];
            ax += a0*h0.x + a1*h1.x + a2*h2.x + a3*h3.x;
            ay += a0*h0.y + a1*h1.y + a2*h2.y + a3*h3.y;
            az += a0*h0.z + a1*h1.z + a2*h2.z + a3*h3.z;
            aw += a0*h0.w + a1*h1.w + a2*h2.w + a3*h3.w;
        }
        for (; k < cnt; k++) {
            float a = al[k * HEADS + hd];
            const float4 h = *(const float4*)&g_h1[(size_t)sSrc[k] * H1DIM + o4];
            ax += a * h.x; ay += a * h.y; az += a * h.z; aw += a * h.w;
        }
        float4 bb = *(const float4*)&b1[o4];
        *(float4*)&sX[o4] = make_float4(fmaxf(ax + bb.x, 0.f), fmaxf(ay + bb.y, 0.f),
                                        fmaxf(az + bb.z, 0.f), fmaxf(aw + bb.w, 0.f));
    }
    __syncthreads();
    // gemm2: h2 row = sX @ W2T, warp per output
    for (int o = w; o < OUTD; o += 8) {
        const float* wr = &g_W2T[o * H1DIM];
        float s = 0.f;
        for (int c = lane * 4; c < H1DIM; c += 128) {
            float4 xv = *(const float4*)&sX[c];
            float4 wv = *(const float4*)&wr[c];
            s += xv.x * wv.x + xv.y * wv.y + xv.z * wv.z + xv.w * wv.w;
        }
#pragma unroll
        for (int o2 = 16; o2; o2 >>= 1) s += __shfl_down_sync(0xffffffffu, s, o2);
        if (!lane) { g_h2[tnode * OUTD + o] = s; lg[o] = s; }
    }
    __syncthreads();
    if (tid == 0) {
        float s = 0.f, d = 0.f;
        for (int oo = 0; oo < OUTD; oo++) {
            s += lg[oo] * a_src2[oo];
            d += lg[oo] * a_dst2[oo];
        }
        g_ss2[tnode] = s; g_ds2[tnode] = d;
    }
}

// ---------------- K5: GAT2 edge-sliced aggregate -> logits + labels --------
__global__ void k_gat2(const float* __restrict__ b2, float* __restrict__ out,
                       int out_size) {
    int tnode = blockIdx.x, tid = threadIdx.x;   // 256 threads
    int off = g_off[tnode], cnt = g_off[tnode + 1] - off;
    __shared__ int   sSrc[E_TOT];
    __shared__ float al[E_TOT];
    __shared__ float red[2];            // m, inv_sum
    __shared__ float partial[8][24];
    __shared__ float lg[OUTD];
    for (int k = tid; k < cnt; k += 256) {
        int sn = edge_src(g_inc[off + k]);
        sSrc[k] = sn;
        float x = g_ss2[sn] + g_ds2[tnode];
        al[k] = (x >= 0.f) ? x : 0.2f * x;
    }
    __syncthreads();
    // warp 0: max + sum
    if (tid < 32) {
        float m = -INFINITY;
        for (int k = tid; k < cnt; k += 32) m = fmaxf(m, al[k]);
#pragma unroll
        for (int o = 16; o; o >>= 1) m = fmaxf(m, __shfl_xor_sync(0xffffffffu, m, o));
        float s = 0.f;
        for (int k = tid; k < cnt; k += 32) s += expf(al[k] - m);
#pragma unroll
        for (int o = 16; o; o >>= 1) s += __shfl_xor_sync(0xffffffffu, s, o);
        if (tid == 0) { red[0] = m; red[1] = 1.f / s; }
    }
    __syncthreads();
    float m = red[0], inv = red[1];
    for (int k = tid; k < cnt; k += 256) al[k] = expf(al[k] - m) * inv;
    __syncthreads();
    // edge-sliced aggregation: 8 slices x 32 lanes (o < 21 active)
    {
        int es = tid >> 5, o = tid & 31;
        float acc = 0.f;
        if (o < OUTD)
            for (int k = es; k < cnt; k += 8)
                acc += al[k] * g_h2[sSrc[k] * OUTD + o];
        partial[es][o & 23] = acc;      // o<24 always when active
        if (o < OUTD) partial[es][o] = acc;
    }
    __syncthreads();
    if (tid < OUTD) {
        float v = b2[tid];
#pragma unroll
        for (int es = 0; es < 8; es++) v += partial[es][tid];
        lg[tid] = v;
        out[tnode * OUTD + tid] = v;
    }
    __syncthreads();
    if (tid == 0 && out_size >= NN * OUTD + NN) {
        int best = 0;
        float bv = lg[0];
        for (int o = 1; o < OUTD; o++)
            if (lg[o] > bv) { bv = lg[o]; best = o; }
        out[NN * OUTD + tnode] = (float)best;
    }
}

// ---------------------------------------------------------------------------
extern "C" void kernel_launch(void* const* d_in, const int* in_sizes, int n_in,
                              void* d_out, int out_size) {
    const float* features = (const float*)d_in[0];
    const float* boxes    = (const float*)d_in[1];
    const float* W_fc1    = (const float*)d_in[2];
    const float* b_fc1    = (const float*)d_in[3];
    const float* W_fc2    = (const float*)d_in[4];
    const float* b_fc2    = (const float*)d_in[5];
    const float* W1       = (const float*)d_in[6];
    const float* a_src1   = (const float*)d_in[7];
    const float* a_dst1   = (const float*)d_in[8];
    const float* b1       = (const float*)d_in[9];
    const float* W2       = (const float*)d_in[10];
    const float* a_src2   = (const float*)d_in[11];
    const float* a_dst2   = (const float*)d_in[12];
    const float* b2       = (const float*)d_in[13];
    const void*  img_h    = d_in[14];
    const void*  img_w    = d_in[15];
    float* out = (float*)d_out;

    k_mm<<<192, 512>>>(features, W_fc1, W1, boxes, img_h, img_w);
    k_rel<<<dim3(4, 32), 128>>>(boxes, W_fc1, b_fc1, W_fc2, b_fc2);
    k_topk_score<<<33, 1024>>>(W2, a_src1, a_dst1);
    k_gat1f<<<NN, 256>>>(b1, a_src2, a_dst2);
    k_gat2<<<NN, 256>>>(b2, out, out_size);
}

// round 14
// speedup vs baseline: 1.6294x; 1.0784x over previous
#include <cuda_runtime.h>
#include <math.h>

#define NN    256
#define FEATD 1024
#define HIDR  256
#define HEADS 4
#define GCH   256
#define H1DIM 1024   // HEADS*GCH
#define OUTD  21
#define TOPK  3
#define E_TOT (NN*TOPK + NN)   // 1024 edges

// ---------------- scratch (device globals; no allocation allowed) ----------
__device__ __align__(16) float g_A[NN*HIDR];
__device__ __align__(16) float g_B[NN*HIDR];
__device__ __align__(16) float g_rel[NN*NN];
__device__ int   g_off[NN+1];
__device__ int   g_inc[E_TOT];
__device__ __align__(16) float g_h1[NN*H1DIM];
__device__ float g_ss1[NN*HEADS], g_ds1[NN*HEADS];
__device__ __align__(16) float g_h2[NN*OUTD];
__device__ float g_ss2[NN], g_ds2[NN];
__device__ __align__(16) float g_W2T[OUTD*H1DIM];   // W2 transposed [o][c]

// edge id -> source node (edges 0..767 are topk from row e/3; 768.. are loops)
__device__ __forceinline__ int edge_src(int e) {
    return (e < NN * TOPK) ? (e / TOPK) : (e - NN * TOPK);
}

// read a scalar that may have been serialized as int32 or float32
__device__ __forceinline__ float read_dim(const void* p) {
    int iv = *(const int*)p;
    if (iv > 0 && iv < 100000) return (float)iv;
    return *(const float*)p;
}

// ---------------- K1: combined GEMMs, 4-way split-K, 2 blocks/SM -----------
struct Acc44 { float a[4][4]; };

__global__ __launch_bounds__(512, 2)
void k_mm(const float* __restrict__ feat, const float* __restrict__ Wfc1,
          const float* __restrict__ W1, const float* __restrict__ boxes,
          const void* img_h, const void* img_w) {
    __shared__ float sbuf[6600];             // 4x tile sets (6400) / reduction (6528)
    int b = blockIdx.x;
    int t = threadIdx.x;
    int q = t >> 7, ht = t & 127;
    int tx4 = (ht & 15) * 4, ty4 = (ht >> 4) * 4;

    const float* W;
    float* dst;
    int row0, colL, ldw;
    bool gemm1 = (b >= 64);
    if (!gemm1) {
        int col0g = (b & 7) * 64;
        row0 = (b >> 3) * 32;
        ldw = HIDR;
        if (col0g < 256) { W = Wfc1;                       dst = g_A; colL = col0g; }
        else             { W = Wfc1 + (size_t)1024 * HIDR; dst = g_B; colL = col0g - 256; }
    } else {
        int i = b - 64;
        colL = (i & 15) * 64;
        row0 = (i >> 4) * 32;
        ldw = H1DIM;
        W = W1;
        dst = g_h1;
    }

    float* reg = sbuf + q * 1600;
    float (*sAT)[36] = (float (*)[36])reg;
    float (*sW)[64]  = (float (*)[64])(reg + 16 * 36);

    int arow = ht >> 2, akq = ht & 3;
    int wkr  = ht >> 3, wcq = ht & 7;
    int k0 = q * 256;                        // quarter of K=1024
    const float* Aptr = feat + (size_t)(row0 + arow) * FEATD + k0 + akq * 4;
    const float* Wptr = W + (size_t)(k0 + wkr) * ldw + colL + wcq * 8;

    Acc44 acc = {};
    float4 pa  = *(const float4*)Aptr;
    float4 pw0 = *(const float4*)Wptr;
    float4 pw1 = *(const float4*)(Wptr + 4);
#pragma unroll 1
    for (int kt = 0; kt < 16; kt++) {
        sAT[akq*4+0][arow] = pa.x;
        sAT[akq*4+1][arow] = pa.y;
        sAT[akq*4+2][arow] = pa.z;
        sAT[akq*4+3][arow] = pa.w;
        *(float4*)&sW[wkr][wcq*8]     = pw0;
        *(float4*)&sW[wkr][wcq*8 + 4] = pw1;
        __syncthreads();
        if (kt + 1 < 16) {
            const float* An = Aptr + (kt + 1) * 16;
            const float* Wn = Wptr + (size_t)(kt + 1) * 16 * ldw;
            pa  = *(const float4*)An;
            pw0 = *(const float4*)Wn;
            pw1 = *(const float4*)(Wn + 4);
        }
#pragma unroll
        for (int kk = 0; kk < 16; kk++) {
            float4 a = *(const float4*)&sAT[kk][ty4];
            float4 w = *(const float4*)&sW[kk][tx4];
            acc.a[0][0] += a.x * w.x; acc.a[0][1] += a.x * w.y; acc.a[0][2] += a.x * w.z; acc.a[0][3] += a.x * w.w;
            acc.a[1][0] += a.y * w.x; acc.a[1][1] += a.y * w.y; acc.a[1][2] += a.y * w.z; acc.a[1][3] += a.y * w.w;
            acc.a[2][0] += a.z * w.x; acc.a[2][1] += a.z * w.y; acc.a[2][2] += a.z * w.z; acc.a[2][3] += a.z * w.w;
            acc.a[3][0] += a.w * w.x; acc.a[3][1] += a.w * w.y; acc.a[3][2] += a.w * w.z; acc.a[3][3] += a.w * w.w;
        }
        __syncthreads();
    }

    // reduction: quarters 1..3 dump accs (stride 17 -> conflict-free), q0 sums
    if (q > 0) {
        float* rb = sbuf + (q - 1) * 2176 + ht * 17;
#pragma unroll
        for (int u = 0; u < 4; u++)
#pragma unroll
            for (int j = 0; j < 4; j++)
                rb[u * 4 + j] = acc.a[u][j];
    }
    __syncthreads();
    if (q == 0) {
#pragma unroll
        for (int r = 0; r < 3; r++) {
            float* rb = sbuf + r * 2176 + ht * 17;
#pragma unroll
            for (int u = 0; u < 4; u++)
#pragma unroll
                for (int j = 0; j < 4; j++)
                    acc.a[u][j] += rb[u * 4 + j];
        }
        if (gemm1) {
            float fw = read_dim(img_w), fh = read_dim(img_h);
#pragma unroll
            for (int u = 0; u < 4; u++) {
                int n = row0 + ty4 + u;
                float b0 = boxes[n*4+0] / fw, b1 = boxes[n*4+1] / fh;
                float b2 = boxes[n*4+2] / fw, b3 = boxes[n*4+3] / fh;
                float G[4] = { b0, b1, b2 - b0, b3 - b1 };
#pragma unroll
                for (int kk = 0; kk < 4; kk++) {
                    float4 w = *(const float4*)&W1[(size_t)(FEATD + kk) * H1DIM + colL + tx4];
                    acc.a[u][0] += G[kk] * w.x;
                    acc.a[u][1] += G[kk] * w.y;
                    acc.a[u][2] += G[kk] * w.z;
                    acc.a[u][3] += G[kk] * w.w;
                }
            }
        }
#pragma unroll
        for (int u = 0; u < 4; u++) {
            int r = row0 + ty4 + u;
            *(float4*)&dst[(size_t)r * ldw + colL + tx4] =
                make_float4(acc.a[u][0], acc.a[u][1], acc.a[u][2], acc.a[u][3]);
        }
    }
}

// ---------------- K2: rel[i,j] = relu(A[i]+B[j]+bias+geom@Wg) . W_fc2 + b2 -
__global__ void k_rel(const float* __restrict__ boxes,
                      const float* __restrict__ Wfc1,
                      const float* __restrict__ bfc1,
                      const float* __restrict__ Wfc2,
                      const float* __restrict__ bfc2) {
    __shared__ __align__(16) float sAb[8][HIDR];
    __shared__ __align__(16) float sBt[HIDR][68];
    __shared__ __align__(16) float4 sGeo[HIDR];
    __shared__ float sW2[HIDR];
    int t = threadIdx.x;                 // 128
    int il = t >> 4, jg = t & 15, jl = jg * 4;
    int i0 = blockIdx.y * 8, j0 = blockIdx.x * 64;
    const float* Wg = Wfc1 + (size_t)2 * FEATD * HIDR;
    for (int idx = t; idx < 8 * HIDR; idx += 128) {
        int i = idx >> 8, c = idx & 255;
        sAb[i][c] = g_A[(size_t)(i0 + i) * HIDR + c] + bfc1[c];
    }
    for (int idx = t; idx < 64 * HIDR; idx += 128) {
        int j = idx >> 8, c = idx & 255;
        sBt[c][j] = g_B[(size_t)(j0 + j) * HIDR + c];
    }
    for (int c = t; c < HIDR; c += 128) {
        sGeo[c] = make_float4(Wg[c], Wg[HIDR + c], Wg[2 * HIDR + c], Wg[3 * HIDR + c]);
        sW2[c] = Wfc2[c];
    }
    __syncthreads();
    int ig = i0 + il;
    float bi0 = boxes[ig*4+0], bi1 = boxes[ig*4+1], bi2 = boxes[ig*4+2], bi3 = boxes[ig*4+3];
    float4 G[4];
#pragma unroll
    for (int q = 0; q < 4; q++) {
        int jgl = j0 + jl + q;
        G[q] = make_float4(fabsf(bi0 - boxes[jgl*4+0]), fabsf(bi1 - boxes[jgl*4+1]),
                           fabsf(bi2 - boxes[jgl*4+2]), fabsf(bi3 - boxes[jgl*4+3]));
    }
    float acc[4] = {};
#pragma unroll 4
    for (int c = 0; c < HIDR; c++) {
        float  a  = sAb[il][c];
        float4 wg = sGeo[c];
        float  w2 = sW2[c];
        float4 b4 = *(const float4*)&sBt[c][jl];
        float v0 = a + b4.x + G[0].x*wg.x + G[0].y*wg.y + G[0].z*wg.z + G[0].w*wg.w;
        float v1 = a + b4.y + G[1].x*wg.x + G[1].y*wg.y + G[1].z*wg.z + G[1].w*wg.w;
        float v2 = a + b4.z + G[2].x*wg.x + G[2].y*wg.y + G[2].z*wg.z + G[2].w*wg.w;
        float v3 = a + b4.w + G[3].x*wg.x + G[3].y*wg.y + G[3].z*wg.z + G[3].w*wg.w;
        acc[0] += fmaxf(v0, 0.f) * w2;
        acc[1] += fmaxf(v1, 0.f) * w2;
        acc[2] += fmaxf(v2, 0.f) * w2;
        acc[3] += fmaxf(v3, 0.f) * w2;
    }
    float bb = bfc2[0];
#pragma unroll
    for (int q = 0; q < 4; q++)
        g_rel[(size_t)ig * NN + j0 + jl + q] = acc[q] + bb;
}

// ---------------- K3: block 0 = topk + CSR + W2T; blocks 1..32 = score1 ----
__global__ void k_topk_score(const float* __restrict__ W2,
                             const float* __restrict__ a_src,
                             const float* __restrict__ a_dst) {
    int t = threadIdx.x;                 // 1024
    int lane = t & 31, w = t >> 5;
    if (blockIdx.x > 0) {
        // ---- score1: 8 nodes per block, 128 threads per node ----
        int n = (blockIdx.x - 1) * 8 + (t >> 7);
        int wt = t & 127;
        int hd = wt >> 5;
        float s = 0.f, d = 0.f;
        const float* hr = &g_h1[(size_t)n * H1DIM + hd * GCH];
        for (int c = lane; c < GCH; c += 32) {
            float hv = hr[c];
            s += hv * a_src[hd * GCH + c];
            d += hv * a_dst[hd * GCH + c];
        }
#pragma unroll
        for (int o = 16; o; o >>= 1) {
            s += __shfl_down_sync(0xffffffffu, s, o);
            d += __shfl_down_sync(0xffffffffu, d, o);
        }
        if (!lane) { g_ss1[n * HEADS + hd] = s; g_ds1[n * HEADS + hd] = d; }
        return;
    }
    // ---- block 0: topk + CSR + W2T ----
    __shared__ int sTop[NN * TOPK];
    __shared__ int M[32][NN];
    __shared__ int off[NN];
    for (int idx = t; idx < 32 * NN; idx += 1024) ((int*)M)[idx] = 0;
    for (int i = w; i < NN; i += 32) {
        float v[8];
#pragma unroll
        for (int q = 0; q < 8; q++) v[q] = g_rel[i * NN + q * 32 + lane];
#pragma unroll
        for (int sel = 0; sel < TOPK + 1; sel++) {
            float bv = -INFINITY; int bi = 0;
#pragma unroll
            for (int q = 0; q < 8; q++) {
                int idx = q * 32 + lane;
                if (v[q] > bv) { bv = v[q]; bi = idx; }
            }
#pragma unroll
            for (int o = 16; o; o >>= 1) {
                float ov = __shfl_down_sync(0xffffffffu, bv, o);
                int   oi = __shfl_down_sync(0xffffffffu, bi, o);
                if (ov > bv || (ov == bv && oi < bi)) { bv = ov; bi = oi; }
            }
            bi = __shfl_sync(0xffffffffu, bi, 0);
            if (sel > 0 && lane == 0) sTop[i * TOPK + sel - 1] = bi;
            if ((bi & 31) == lane) v[bi >> 5] = -INFINITY;
        }
    }
    for (int idx = t; idx < OUTD * H1DIM; idx += 1024) {
        int o = idx / H1DIM, c = idx - o * H1DIM;
        g_W2T[idx] = W2[c * OUTD + o];
    }
    __syncthreads();
    int e = t;
    int tg = (e < NN * TOPK) ? sTop[e] : (e - NN * TOPK);
    unsigned same = __match_any_sync(0xffffffffu, tg);
    int rank = __popc(same & ((1u << lane) - 1u));
    if (rank == 0) M[w][tg] = __popc(same);
    __syncthreads();
    if (t < NN) {
        int run = 0;
#pragma unroll
        for (int cc = 0; cc < 32; cc++) { int v = M[cc][t]; M[cc][t] = run; run += v; }
        off[t] = run;
    }
    __syncthreads();
    for (int s = 1; s < NN; s <<= 1) {
        int v = 0;
        if (t < NN && t >= s) v = off[t - s];
        __syncthreads();
        if (t < NN) off[t] += v;
        __syncthreads();
    }
    if (t < NN) {
        g_off[t + 1] = off[t];
        if (t == 0) g_off[0] = 0;
    }
    __syncthreads();
    int base = (tg == 0) ? 0 : off[tg - 1];
    g_inc[base + M[w][tg] + rank] = e;
}

// ---------------- K4: fused GAT1 agg (2 edge-slices) + gemm2 + scores2 -----
__global__ __launch_bounds__(512)
void k_gat1f(const float* __restrict__ b1,
             const float* __restrict__ a_src2,
             const float* __restrict__ a_dst2) {
    int tnode = blockIdx.x, tid = threadIdx.x;   // 512 threads
    int w = tid >> 5, lane = tid & 31;
    int off = g_off[tnode], cnt = g_off[tnode + 1] - off;
    __shared__ int   sSrc[E_TOT];
    __shared__ float al[E_TOT * HEADS];
    __shared__ __align__(16) float sX[H1DIM];
    __shared__ __align__(16) float sXp[H1DIM];   // slice-1 partials
    __shared__ float lg[OUTD];
    for (int k = tid; k < cnt; k += 512) sSrc[k] = edge_src(g_inc[off + k]);
    __syncthreads();
    for (int idx = tid; idx < cnt * HEADS; idx += 512) {
        int k = idx >> 2, hd = idx & 3;
        float x = g_ss1[sSrc[k] * HEADS + hd] + g_ds1[tnode * HEADS + hd];
        al[idx] = (x >= 0.f) ? x : 0.2f * x;   // leaky_relu 0.2
    }
    __syncthreads();
    // warp-parallel softmax per head (warps 0..3)
    if (w < HEADS) {
        float m = -INFINITY;
        for (int k = lane; k < cnt; k += 32) m = fmaxf(m, al[k * HEADS + w]);
#pragma unroll
        for (int o = 16; o; o >>= 1) m = fmaxf(m, __shfl_xor_sync(0xffffffffu, m, o));
        float s = 0.f;
        for (int k = lane; k < cnt; k += 32) {
            float p = expf(al[k * HEADS + w] - m);
            al[k * HEADS + w] = p;
            s += p;
        }
#pragma unroll
        for (int o = 16; o; o >>= 1) s += __shfl_xor_sync(0xffffffffu, s, o);
        float inv = 1.f / s;
        for (int k = lane; k < cnt; k += 32) al[k * HEADS + w] *= inv;
    }
    __syncthreads();
    // aggregation: 2 edge-slices x 256 output-threads; unroll-by-4 per slice
    {
        int slice = tid >> 8, ot = tid & 255;
        int o4 = ot * 4;
        int hd = o4 >> 8;
        float ax = 0.f, ay = 0.f, az = 0.f, aw = 0.f;
        int k = slice;
        for (; k + 6 < cnt; k += 8) {
            float a0 = al[(k+0) * HEADS + hd];
            float a1 = al[(k+2) * HEADS + hd];
            float a2 = al[(k+4) * HEADS + hd];
            float a3 = al[(k+6) * HEADS + hd];
            const float4 h0 = *(const float4*)&g_h1[(size_t)sSrc[k+0] * H1DIM + o4];
            const float4 h1 = *(const float4*)&g_h1[(size_t)sSrc[k+2] * H1DIM + o4];
            const float4 h2 = *(const float4*)&g_h1[(size_t)sSrc[k+4] * H1DIM + o4];
            const float4 h3 = *(const float4*)&g_h1[(size_t)sSrc[k+6] * H1DIM + o4];
            ax += a0*h0.x + a1*h1.x + a2*h2.x + a3*h3.x;
            ay += a0*h0.y + a1*h1.y + a2*h2.y + a3*h3.y;
            az += a0*h0.z + a1*h1.z + a2*h2.z + a3*h3.z;
            aw += a0*h0.w + a1*h1.w + a2*h2.w + a3*h3.w;
        }
        for (; k < cnt; k += 2) {
            float a = al[k * HEADS + hd];
            const float4 h = *(const float4*)&g_h1[(size_t)sSrc[k] * H1DIM + o4];
            ax += a * h.x; ay += a * h.y; az += a * h.z; aw += a * h.w;
        }
        if (slice == 1) {
            *(float4*)&sXp[o4] = make_float4(ax, ay, az, aw);
        }
        __syncthreads();
        if (slice == 0) {
            float4 p = *(const float4*)&sXp[o4];
            float4 bb = *(const float4*)&b1[o4];
            *(float4*)&sX[o4] = make_float4(
                fmaxf(ax + p.x + bb.x, 0.f), fmaxf(ay + p.y + bb.y, 0.f),
                fmaxf(az + p.z + bb.z, 0.f), fmaxf(aw + p.w + bb.w, 0.f));
        }
    }
    __syncthreads();
    // gemm2: h2 row = sX @ W2T, warp per output (16 warps)
    for (int o = w; o < OUTD; o += 16) {
        const float* wr = &g_W2T[o * H1DIM];
        float s = 0.f;
        for (int c = lane * 4; c < H1DIM; c += 128) {
            float4 xv = *(const float4*)&sX[c];
            float4 wv = *(const float4*)&wr[c];
            s += xv.x * wv.x + xv.y * wv.y + xv.z * wv.z + xv.w * wv.w;
        }
#pragma unroll
        for (int o2 = 16; o2; o2 >>= 1) s += __shfl_down_sync(0xffffffffu, s, o2);
        if (!lane) { g_h2[tnode * OUTD + o] = s; lg[o] = s; }
    }
    __syncthreads();
    if (tid == 0) {
        float s = 0.f, d = 0.f;
        for (int oo = 0; oo < OUTD; oo++) {
            s += lg[oo] * a_src2[oo];
            d += lg[oo] * a_dst2[oo];
        }
        g_ss2[tnode] = s; g_ds2[tnode] = d;
    }
}

// ---------------- K5: GAT2 edge-sliced aggregate -> logits + labels --------
__global__ void k_gat2(const float* __restrict__ b2, float* __restrict__ out,
                       int out_size) {
    int tnode = blockIdx.x, tid = threadIdx.x;   // 256 threads
    int off = g_off[tnode], cnt = g_off[tnode + 1] - off;
    __shared__ int   sSrc[E_TOT];
    __shared__ float al[E_TOT];
    __shared__ float red[2];            // m, inv_sum
    __shared__ float partial[8][32];
    __shared__ float lg[OUTD];
    for (int k = tid; k < cnt; k += 256) {
        int sn = edge_src(g_inc[off + k]);
        sSrc[k] = sn;
        float x = g_ss2[sn] + g_ds2[tnode];
        al[k] = (x >= 0.f) ? x : 0.2f * x;
    }
    __syncthreads();
    // warp 0: max + sum
    if (tid < 32) {
        float m = -INFINITY;
        for (int k = tid; k < cnt; k += 32) m = fmaxf(m, al[k]);
#pragma unroll
        for (int o = 16; o; o >>= 1) m = fmaxf(m, __shfl_xor_sync(0xffffffffu, m, o));
        float s = 0.f;
        for (int k = tid; k < cnt; k += 32) s += expf(al[k] - m);
#pragma unroll
        for (int o = 16; o; o >>= 1) s += __shfl_xor_sync(0xffffffffu, s, o);
        if (tid == 0) { red[0] = m; red[1] = 1.f / s; }
    }
    __syncthreads();
    float m = red[0], inv = red[1];
    for (int k = tid; k < cnt; k += 256) al[k] = expf(al[k] - m) * inv;
    __syncthreads();
    // edge-sliced aggregation: 8 slices x 32 lanes (o < 21 active)
    {
        int es = tid >> 5, o = tid & 31;
        if (o < OUTD) {
            float acc = 0.f;
            for (int k = es; k < cnt; k += 8)
                acc += al[k] * g_h2[sSrc[k] * OUTD + o];
            partial[es][o] = acc;
        }
    }
    __syncthreads();
    if (tid < OUTD) {
        float v = b2[tid];
#pragma unroll
        for (int es = 0; es < 8; es++) v += partial[es][tid];
        lg[tid] = v;
        out[tnode * OUTD + tid] = v;
    }
    __syncthreads();
    if (tid == 0 && out_size >= NN * OUTD + NN) {
        int best = 0;
        float bv = lg[0];
        for (int o = 1; o < OUTD; o++)
            if (lg[o] > bv) { bv = lg[o]; best = o; }
        out[NN * OUTD + tnode] = (float)best;
    }
}

// ---------------------------------------------------------------------------
extern "C" void kernel_launch(void* const* d_in, const int* in_sizes, int n_in,
                              void* d_out, int out_size) {
    const float* features = (const float*)d_in[0];
    const float* boxes    = (const float*)d_in[1];
    const float* W_fc1    = (const float*)d_in[2];
    const float* b_fc1    = (const float*)d_in[3];
    const float* W_fc2    = (const float*)d_in[4];
    const float* b_fc2    = (const float*)d_in[5];
    const float* W1       = (const float*)d_in[6];
    const float* a_src1   = (const float*)d_in[7];
    const float* a_dst1   = (const float*)d_in[8];
    const float* b1       = (const float*)d_in[9];
    const float* W2       = (const float*)d_in[10];
    const float* a_src2   = (const float*)d_in[11];
    const float* a_dst2   = (const float*)d_in[12];
    const float* b2       = (const float*)d_in[13];
    const void*  img_h    = d_in[14];
    const void*  img_w    = d_in[15];
    float* out = (float*)d_out;

    k_mm<<<192, 512>>>(features, W_fc1, W1, boxes, img_h, img_w);
    k_rel<<<dim3(4, 32), 128>>>(boxes, W_fc1, b_fc1, W_fc2, b_fc2);
    k_topk_score<<<33, 1024>>>(W2, a_src1, a_dst1);
    k_gat1f<<<NN, 512>>>(b1, a_src2, a_dst2);
    k_gat2<<<NN, 256>>>(b2, out, out_size);
}